// round 1
// baseline (speedup 1.0000x reference)
#include <cuda_runtime.h>
#include <cuda_bf16.h>

// Problem constants (match reference setup_inputs)
#define NN 100000
#define EE 3200000
#define SCAN_B 512
#define NBLK_SCAN ((NN + SCAN_B - 1) / SCAN_B)

// -------- device scratch (static allocation; no cudaMalloc allowed) --------
__device__ float g_p[NN * 128];      // p = dis * (h @ W)
__device__ float g_h[NN * 128];      // current hidden
__device__ float g_o3[NN * 192];     // concatenated scale outputs
__device__ float g_dis[NN];
__device__ int   g_deg[NN];
__device__ int   g_rowptr[NN];
__device__ int   g_cursor[NN];
__device__ int   g_col[EE];
__device__ int   g_bsum[NBLK_SCAN + 1];

// ---------------------------------------------------------------------------
// graph prep kernels
// ---------------------------------------------------------------------------
__global__ void zero_kernel(int* deg, int* cur, int n) {
    int i = blockIdx.x * blockDim.x + threadIdx.x;
    if (i < n) { deg[i] = 0; cur[i] = 0; }
}

__global__ void count_kernel(const int* __restrict__ dst, int* __restrict__ deg, int e) {
    int i = blockIdx.x * blockDim.x + threadIdx.x;
    if (i < e) atomicAdd(&deg[dst[i]], 1);
}

__global__ void dis_kernel(const int* __restrict__ deg, float* __restrict__ dis, int n) {
    int i = blockIdx.x * blockDim.x + threadIdx.x;
    if (i < n) dis[i] = rsqrtf((float)deg[i] + 1.0f);
}

// exclusive scan, 3 phases
__global__ void scan1_kernel(const int* __restrict__ deg, int* __restrict__ out,
                             int* __restrict__ bsum, int n) {
    __shared__ int sh[SCAN_B];
    int tid = threadIdx.x;
    int i = blockIdx.x * SCAN_B + tid;
    int v = (i < n) ? deg[i] : 0;
    sh[tid] = v;
    __syncthreads();
#pragma unroll
    for (int off = 1; off < SCAN_B; off <<= 1) {
        int t = (tid >= off) ? sh[tid - off] : 0;
        __syncthreads();
        sh[tid] += t;
        __syncthreads();
    }
    if (i < n) out[i] = sh[tid] - v;  // exclusive
    if (tid == SCAN_B - 1) bsum[blockIdx.x] = sh[tid];
}

__global__ void scan2_kernel(int* bsum, int nb) {
    if (threadIdx.x == 0 && blockIdx.x == 0) {
        int acc = 0;
        for (int i = 0; i < nb; i++) { int t = bsum[i]; bsum[i] = acc; acc += t; }
    }
}

__global__ void scan3_kernel(int* __restrict__ out, const int* __restrict__ bsum, int n) {
    int i = blockIdx.x * blockDim.x + threadIdx.x;
    if (i < n) out[i] += bsum[i / SCAN_B];
}

__global__ void fill_kernel(const int* __restrict__ src, const int* __restrict__ dst,
                            const int* __restrict__ rowptr, int* __restrict__ cur,
                            int* __restrict__ col, int e) {
    int i = blockIdx.x * blockDim.x + threadIdx.x;
    if (i < e) {
        int d = dst[i];
        int pos = rowptr[d] + atomicAdd(&cur[d], 1);
        col[pos] = src[i];
    }
}

// ---------------------------------------------------------------------------
// tiled fp32 GEMM:  C[nrows, BN] = A[nrows, KDIM] @ W[KDIM, BN]
// MODE 0: C = dis[row] * (A@W)      (produces p)
// MODE 1: C = A@W + bias            (final fusion)
// ---------------------------------------------------------------------------
template <int KDIM, int BN, int MODE>
__global__ void __launch_bounds__(256)
gemm_kernel(const float* __restrict__ A, const float* __restrict__ W,
            const float* __restrict__ dis, const float* __restrict__ bias,
            float* __restrict__ C, int nrows) {
    constexpr int BM = 128, BK = 16;
    constexpr int TM = 8, TN = BN / 16;
    __shared__ float As[BK][BM + 4];
    __shared__ float Ws[BK][BN];

    int tid = threadIdx.x;
    int m0 = blockIdx.x * BM;
    int rb = (tid / 16) * TM;
    int cb = (tid % 16) * TN;

    float acc[TM][TN];
#pragma unroll
    for (int i = 0; i < TM; i++)
#pragma unroll
        for (int j = 0; j < TN; j++) acc[i][j] = 0.0f;

    for (int kk = 0; kk < KDIM; kk += BK) {
        // load A tile (transposed into shared)
#pragma unroll
        for (int t = 0; t < (BM * BK) / 256; t++) {
            int idx = t * 256 + tid;
            int m = idx / BK, k = idx % BK;
            int row = m0 + m;
            As[k][m] = (row < nrows) ? A[row * KDIM + kk + k] : 0.0f;
        }
        // load W tile
#pragma unroll
        for (int t = 0; t < (BK * BN) / 256; t++) {
            int idx = t * 256 + tid;
            int k = idx / BN, c = idx % BN;
            Ws[k][c] = W[(kk + k) * BN + c];
        }
        __syncthreads();
#pragma unroll
        for (int k = 0; k < BK; k++) {
            float a[TM], w[TN];
#pragma unroll
            for (int i = 0; i < TM; i++) a[i] = As[k][rb + i];
#pragma unroll
            for (int j = 0; j < TN; j++) w[j] = Ws[k][cb + j];
#pragma unroll
            for (int i = 0; i < TM; i++)
#pragma unroll
                for (int j = 0; j < TN; j++) acc[i][j] = fmaf(a[i], w[j], acc[i][j]);
        }
        __syncthreads();
    }

#pragma unroll
    for (int i = 0; i < TM; i++) {
        int row = m0 + rb + i;
        if (row < nrows) {
            if (MODE == 0) {
                float sc = dis[row];
#pragma unroll
                for (int j = 0; j < TN; j++) C[row * BN + cb + j] = sc * acc[i][j];
            } else {
#pragma unroll
                for (int j = 0; j < TN; j++) C[row * BN + cb + j] = acc[i][j] + bias[cb + j];
            }
        }
    }
}

// ---------------------------------------------------------------------------
// aggregation + (optional ReLU + LayerNorm)
// out_row(v) = dis[v] * ( sum_{u in N(v)} p[u] + p[v] ) + bias
// One block per node, D threads (feature-parallel), coalesced gathers from L2.
// ---------------------------------------------------------------------------
template <int D, bool LNRELU>
__global__ void __launch_bounds__(128)
agg_kernel(const float* __restrict__ p, const float* __restrict__ dis,
           const int* __restrict__ rowptr, const int* __restrict__ deg,
           const int* __restrict__ col,
           const float* __restrict__ bias, const float* __restrict__ gamma,
           const float* __restrict__ beta,
           float* __restrict__ out, int ldo, int col_off) {
    int v = blockIdx.x;
    int t = threadIdx.x;  // 0..D-1
    __shared__ int scol[128];

    int start = rowptr[v];
    int d = deg[v];
    float sum = p[v * D + t];  // self-loop term (p already carries dis)

    for (int c0 = 0; c0 < d; c0 += D) {
        int c = min(D, d - c0);
        __syncthreads();
        if (t < c) scol[t] = col[start + c0 + t];
        __syncthreads();
#pragma unroll 4
        for (int j = 0; j < c; j++) sum += p[scol[j] * D + t];
    }

    float val = dis[v] * sum + bias[t];

    if (LNRELU) {
        val = fmaxf(val, 0.0f);
        // block reduce sum & sumsq over D threads
        float s1 = val, s2 = val * val;
#pragma unroll
        for (int o = 16; o > 0; o >>= 1) {
            s1 += __shfl_down_sync(0xffffffffu, s1, o);
            s2 += __shfl_down_sync(0xffffffffu, s2, o);
        }
        __shared__ float r1[4], r2[4];
        int w = t >> 5, lane = t & 31;
        if (lane == 0) { r1[w] = s1; r2[w] = s2; }
        __syncthreads();
        float tot1 = 0.0f, tot2 = 0.0f;
#pragma unroll
        for (int i = 0; i < D / 32; i++) { tot1 += r1[i]; tot2 += r2[i]; }
        float mu = tot1 / (float)D;
        float var = tot2 / (float)D - mu * mu;
        float inv = rsqrtf(var + 1e-5f);
        out[v * ldo + col_off + t] = (val - mu) * inv * gamma[t] + beta[t];
    } else {
        out[v * ldo + col_off + t] = val;
    }
}

// ---------------------------------------------------------------------------
// launch
// ---------------------------------------------------------------------------
extern "C" void kernel_launch(void* const* d_in, const int* in_sizes, int n_in,
                              void* d_out, int out_size) {
    const float* x     = (const float*)d_in[0];
    const int*   ei    = (const int*)d_in[1];
    const float* W0    = (const float*)d_in[2];
    const float* b0    = (const float*)d_in[3];
    const float* W1    = (const float*)d_in[4];
    const float* b1    = (const float*)d_in[5];
    const float* W2    = (const float*)d_in[6];
    const float* b2    = (const float*)d_in[7];
    const float* gamma = (const float*)d_in[8];
    const float* beta  = (const float*)d_in[9];
    const float* Wf    = (const float*)d_in[10];
    const float* bf    = (const float*)d_in[11];
    float* out = (float*)d_out;

    const int N = in_sizes[0] / 128;
    const int E = in_sizes[1] / 2;
    const int* src = ei;
    const int* dst = ei + E;

    float *p, *h, *o3, *dis;
    int *deg, *rp, *cur, *col, *bsum;
    cudaGetSymbolAddress((void**)&p,    g_p);
    cudaGetSymbolAddress((void**)&h,    g_h);
    cudaGetSymbolAddress((void**)&o3,   g_o3);
    cudaGetSymbolAddress((void**)&dis,  g_dis);
    cudaGetSymbolAddress((void**)&deg,  g_deg);
    cudaGetSymbolAddress((void**)&rp,   g_rowptr);
    cudaGetSymbolAddress((void**)&cur,  g_cursor);
    cudaGetSymbolAddress((void**)&col,  g_col);
    cudaGetSymbolAddress((void**)&bsum, g_bsum);

    const int TB = 256;
    int nB = (N + TB - 1) / TB;
    int eB = (E + TB - 1) / TB;
    int nbScan = (N + SCAN_B - 1) / SCAN_B;

    // --- graph prep ---
    zero_kernel<<<nB, TB>>>(deg, cur, N);
    count_kernel<<<eB, TB>>>(dst, deg, E);
    dis_kernel<<<nB, TB>>>(deg, dis, N);
    scan1_kernel<<<nbScan, SCAN_B>>>(deg, rp, bsum, N);
    scan2_kernel<<<1, 32>>>(bsum, nbScan);
    scan3_kernel<<<nB, TB>>>(rp, bsum, N);
    fill_kernel<<<eB, TB>>>(src, dst, rp, cur, col, E);

    int gB = (N + 127) / 128;  // gemm blocks

    // --- per-scale pipeline ---
    for (int s = 0; s < 3; s++) {
        // layer 0: x -> p -> h (relu+LN)
        gemm_kernel<128, 128, 0><<<gB, 256>>>(x, W0 + s * 128 * 128, dis, nullptr, p, N);
        agg_kernel<128, true><<<N, 128>>>(p, dis, rp, deg, col,
                                          b0 + s * 128,
                                          gamma + (s * 3 + 0) * 128,
                                          beta + (s * 3 + 0) * 128,
                                          h, 128, 0);
        // layer 1: h -> p -> h (relu+LN)
        gemm_kernel<128, 128, 0><<<gB, 256>>>(h, W1 + s * 128 * 128, dis, nullptr, p, N);
        agg_kernel<128, true><<<N, 128>>>(p, dis, rp, deg, col,
                                          b1 + s * 128,
                                          gamma + (s * 3 + 1) * 128,
                                          beta + (s * 3 + 1) * 128,
                                          h, 128, 0);
        // layer 2: h -> p64 -> o3 slice (no relu/LN)
        gemm_kernel<128, 64, 0><<<gB, 256>>>(h, W2 + s * 128 * 64, dis, nullptr, p, N);
        agg_kernel<64, false><<<N, 64>>>(p, dis, rp, deg, col,
                                         b2 + s * 64, nullptr, nullptr,
                                         o3, 192, s * 64);
    }

    // --- final fusion: out = o3 @ Wf + bf ---
    gemm_kernel<192, 64, 1><<<gB, 256>>>(o3, Wf, nullptr, bf, out, N);
}

// round 2
// speedup vs baseline: 1.7669x; 1.7669x over previous
#include <cuda_runtime.h>
#include <cuda_bf16.h>

#define NN 100000
#define EE 3200000
#define SCAN_B 512
#define NBLK_SCAN ((NN + SCAN_B - 1) / SCAN_B)

// -------- device scratch (no cudaMalloc allowed) --------
__device__ float g_px[NN * 128];     // dis-prescaled 128-wide buffer (px, then ph per scale)
__device__ float g_y[NN * 128];      // y = A_hat x (shared across scales)
__device__ float g_t[NN * 128];      // t_s = A_hat h_s
__device__ float g_hcat[NN * 384];   // [u_0 | u_1 | u_2]
__device__ float g_pz[NN * 64];      // dis-prescaled tail
__device__ float g_wc[384 * 64];     // Wc_s = W2_s @ Wf_s stacked
__device__ float g_cbias[64];        // b2cat @ Wf + bf
__device__ float g_dis[NN];
__device__ int   g_deg[NN];
__device__ int   g_rowptr[NN];
__device__ int   g_cursor[NN];
__device__ int   g_col[EE];
__device__ int   g_bsum[NBLK_SCAN + 1];

// ---------------------------------------------------------------------------
// graph prep
// ---------------------------------------------------------------------------
__global__ void zero_kernel(int* deg, int* cur, int n) {
    int i = blockIdx.x * blockDim.x + threadIdx.x;
    if (i < n) { deg[i] = 0; cur[i] = 0; }
}

__global__ void count_kernel(const int* __restrict__ dst, int* __restrict__ deg, int e) {
    int i = blockIdx.x * blockDim.x + threadIdx.x;
    if (i < e) atomicAdd(&deg[dst[i]], 1);
}

__global__ void dis_kernel(const int* __restrict__ deg, float* __restrict__ dis, int n) {
    int i = blockIdx.x * blockDim.x + threadIdx.x;
    if (i < n) dis[i] = rsqrtf((float)deg[i] + 1.0f);
}

__global__ void scan1_kernel(const int* __restrict__ deg, int* __restrict__ out,
                             int* __restrict__ bsum, int n) {
    __shared__ int sh[SCAN_B];
    int tid = threadIdx.x;
    int i = blockIdx.x * SCAN_B + tid;
    int v = (i < n) ? deg[i] : 0;
    sh[tid] = v;
    __syncthreads();
#pragma unroll
    for (int off = 1; off < SCAN_B; off <<= 1) {
        int t = (tid >= off) ? sh[tid - off] : 0;
        __syncthreads();
        sh[tid] += t;
        __syncthreads();
    }
    if (i < n) out[i] = sh[tid] - v;
    if (tid == SCAN_B - 1) bsum[blockIdx.x] = sh[tid];
}

__global__ void scan2_kernel(int* bsum, int nb) {
    if (threadIdx.x == 0 && blockIdx.x == 0) {
        int acc = 0;
        for (int i = 0; i < nb; i++) { int t = bsum[i]; bsum[i] = acc; acc += t; }
    }
}

__global__ void scan3_kernel(int* __restrict__ out, const int* __restrict__ bsum, int n) {
    int i = blockIdx.x * blockDim.x + threadIdx.x;
    if (i < n) out[i] += bsum[i / SCAN_B];
}

__global__ void fill_kernel(const int* __restrict__ src, const int* __restrict__ dst,
                            const int* __restrict__ rowptr, int* __restrict__ cur,
                            int* __restrict__ col, int e) {
    int i = blockIdx.x * blockDim.x + threadIdx.x;
    if (i < e) {
        int d = dst[i];
        int pos = rowptr[d] + atomicAdd(&cur[d], 1);
        col[pos] = src[i];
    }
}

// ---------------------------------------------------------------------------
// tiny weight-folding kernels
// Wc[s*128+i, j] = sum_k W2[s,i,k] * Wf[s*64+k, j]
// cbias[j] = sum_{r<192} b2cat[r]*Wf[r,j] + bf[j]
// ---------------------------------------------------------------------------
__global__ void wc_kernel(const float* __restrict__ W2, const float* __restrict__ Wf,
                          float* __restrict__ Wc) {
    int r = blockIdx.x;           // 0..383
    int s = r >> 7, i = r & 127;
    int j = threadIdx.x;          // 0..63
    float acc = 0.0f;
#pragma unroll 8
    for (int k = 0; k < 64; k++)
        acc = fmaf(W2[(s * 128 + i) * 64 + k], Wf[(s * 64 + k) * 64 + j], acc);
    Wc[r * 64 + j] = acc;
}

__global__ void cbias_kernel(const float* __restrict__ b2, const float* __restrict__ Wf,
                             const float* __restrict__ bf, float* __restrict__ cb) {
    int j = threadIdx.x;
    float acc = bf[j];
#pragma unroll 8
    for (int r = 0; r < 192; r++) acc = fmaf(b2[r], Wf[r * 64 + j], acc);
    cb[j] = acc;
}

// px = dis (broadcast over row) * x, float4
__global__ void prescale_kernel(const float4* __restrict__ x, const float* __restrict__ dis,
                                float4* __restrict__ px, int n4) {
    int i = blockIdx.x * blockDim.x + threadIdx.x;
    if (i < n4) {
        float s = dis[i >> 5];   // 32 float4 per row of 128
        float4 v = x[i];
        v.x *= s; v.y *= s; v.z *= s; v.w *= s;
        px[i] = v;
    }
}

// ---------------------------------------------------------------------------
// GEMM: C[nrows, BN] = A[nrows, KDIM] @ W[KDIM, BN], fused epilogues
// EPI 0: LN(relu(acc+bias)) * dis[row]   (BN must be 128)
// EPI 1: LN(relu(acc+bias))              (BN must be 128)
// EPI 2: acc * dis[row]
// ---------------------------------------------------------------------------
template <int KDIM, int BN, int EPI>
__global__ void __launch_bounds__(256)
gemm_kernel(const float* __restrict__ A, const float* __restrict__ W,
            const float* __restrict__ dis, const float* __restrict__ bias,
            const float* __restrict__ gamma, const float* __restrict__ beta,
            float* __restrict__ C, int ldo, int coloff, int nrows) {
    constexpr int BM = 128, BK = 16;
    constexpr int TM = 8, TN = BN / 16;
    __shared__ float As[BK][BM + 4];
    __shared__ float Ws[BK][BN];

    int tid = threadIdx.x;
    int m0 = blockIdx.x * BM;
    int rb = (tid / 16) * TM;
    int cb = (tid % 16) * TN;

    float acc[TM][TN];
#pragma unroll
    for (int i = 0; i < TM; i++)
#pragma unroll
        for (int j = 0; j < TN; j++) acc[i][j] = 0.0f;

    for (int kk = 0; kk < KDIM; kk += BK) {
#pragma unroll
        for (int t = 0; t < (BM * BK) / 256; t++) {
            int idx = t * 256 + tid;
            int m = idx / BK, k = idx % BK;
            int row = m0 + m;
            As[k][m] = (row < nrows) ? A[row * KDIM + kk + k] : 0.0f;
        }
#pragma unroll
        for (int t = 0; t < (BK * BN) / 256; t++) {
            int idx = t * 256 + tid;
            int k = idx / BN, c = idx % BN;
            Ws[k][c] = W[(kk + k) * BN + c];
        }
        __syncthreads();
#pragma unroll
        for (int k = 0; k < BK; k++) {
            float a[TM], w[TN];
#pragma unroll
            for (int i = 0; i < TM; i++) a[i] = As[k][rb + i];
#pragma unroll
            for (int j = 0; j < TN; j++) w[j] = Ws[k][cb + j];
#pragma unroll
            for (int i = 0; i < TM; i++)
#pragma unroll
                for (int j = 0; j < TN; j++) acc[i][j] = fmaf(a[i], w[j], acc[i][j]);
        }
        __syncthreads();
    }

    if (EPI == 2) {
#pragma unroll
        for (int i = 0; i < TM; i++) {
            int row = m0 + rb + i;
            if (row < nrows) {
                float sc = dis[row];
#pragma unroll
                for (int j = 0; j < TN; j++)
                    C[row * ldo + coloff + cb + j] = acc[i][j] * sc;
            }
        }
    } else {
        // fused bias + relu + LayerNorm (full 128-wide row lives in 16 consecutive lanes)
        float bv[TN], gv[TN], tv[TN];
#pragma unroll
        for (int j = 0; j < TN; j++) {
            bv[j] = bias[cb + j]; gv[j] = gamma[cb + j]; tv[j] = beta[cb + j];
        }
#pragma unroll
        for (int i = 0; i < TM; i++) {
            int row = m0 + rb + i;
            float r[TN];
            float s1 = 0.0f, s2 = 0.0f;
#pragma unroll
            for (int j = 0; j < TN; j++) {
                float v = fmaxf(acc[i][j] + bv[j], 0.0f);
                r[j] = v; s1 += v; s2 += v * v;
            }
#pragma unroll
            for (int o = 1; o < 16; o <<= 1) {
                s1 += __shfl_xor_sync(0xffffffffu, s1, o);
                s2 += __shfl_xor_sync(0xffffffffu, s2, o);
            }
            float mu = s1 * (1.0f / 128.0f);
            float var = s2 * (1.0f / 128.0f) - mu * mu;
            float inv = rsqrtf(var + 1e-5f);
            if (row < nrows) {
                float sc = (EPI == 0) ? dis[row] : 1.0f;
#pragma unroll
                for (int j = 0; j < TN; j++)
                    C[row * ldo + coloff + cb + j] =
                        ((r[j] - mu) * inv * gv[j] + tv[j]) * sc;
            }
        }
    }
}

// ---------------------------------------------------------------------------
// aggregation: out[v] = dis[v] * (sum_{u in N(v)} p[u] + p[v])  (warp per node)
// D=128 -> float4 per lane; D=64 -> float2 per lane (+cbias, final output)
// ---------------------------------------------------------------------------
__global__ void __launch_bounds__(256)
agg128_kernel(const float4* __restrict__ p, const float* __restrict__ dis,
              const int* __restrict__ rowptr, const int* __restrict__ deg,
              const int* __restrict__ col, float4* __restrict__ out, int n) {
    int w = (blockIdx.x * blockDim.x + threadIdx.x) >> 5;
    if (w >= n) return;
    int lane = threadIdx.x & 31;
    int start = rowptr[w], d = deg[w];
    float4 a = p[w * 32 + lane];
    float ax = a.x, ay = a.y, az = a.z, aw = a.w;

    int c0 = 0;
    for (; c0 + 32 <= d; c0 += 32) {
        int idx = col[start + c0 + lane];
#pragma unroll 8
        for (int j = 0; j < 32; j++) {
            int u = __shfl_sync(0xffffffffu, idx, j);
            float4 v = p[u * 32 + lane];
            ax += v.x; ay += v.y; az += v.z; aw += v.w;
        }
    }
    int m = d - c0;
    if (m > 0) {
        int idx = (lane < m) ? col[start + c0 + lane] : 0;
        for (int j = 0; j < m; j++) {
            int u = __shfl_sync(0xffffffffu, idx, j);
            float4 v = p[u * 32 + lane];
            ax += v.x; ay += v.y; az += v.z; aw += v.w;
        }
    }
    float s = dis[w];
    float4 o = {ax * s, ay * s, az * s, aw * s};
    out[w * 32 + lane] = o;
}

__global__ void __launch_bounds__(256)
agg64_kernel(const float2* __restrict__ p, const float* __restrict__ dis,
             const int* __restrict__ rowptr, const int* __restrict__ deg,
             const int* __restrict__ col, const float* __restrict__ cbias,
             float2* __restrict__ out, int n) {
    int w = (blockIdx.x * blockDim.x + threadIdx.x) >> 5;
    if (w >= n) return;
    int lane = threadIdx.x & 31;
    int start = rowptr[w], d = deg[w];
    float2 a = p[w * 32 + lane];
    float ax = a.x, ay = a.y;

    int c0 = 0;
    for (; c0 + 32 <= d; c0 += 32) {
        int idx = col[start + c0 + lane];
#pragma unroll 8
        for (int j = 0; j < 32; j++) {
            int u = __shfl_sync(0xffffffffu, idx, j);
            float2 v = p[u * 32 + lane];
            ax += v.x; ay += v.y;
        }
    }
    int m = d - c0;
    if (m > 0) {
        int idx = (lane < m) ? col[start + c0 + lane] : 0;
        for (int j = 0; j < m; j++) {
            int u = __shfl_sync(0xffffffffu, idx, j);
            float2 v = p[u * 32 + lane];
            ax += v.x; ay += v.y;
        }
    }
    float s = dis[w];
    float2 o = {ax * s + cbias[lane * 2], ay * s + cbias[lane * 2 + 1]};
    out[w * 32 + lane] = o;
}

// ---------------------------------------------------------------------------
extern "C" void kernel_launch(void* const* d_in, const int* in_sizes, int n_in,
                              void* d_out, int out_size) {
    const float* x     = (const float*)d_in[0];
    const int*   ei    = (const int*)d_in[1];
    const float* W0    = (const float*)d_in[2];
    const float* b0    = (const float*)d_in[3];
    const float* W1    = (const float*)d_in[4];
    const float* b1    = (const float*)d_in[5];
    const float* W2    = (const float*)d_in[6];
    const float* b2    = (const float*)d_in[7];
    const float* gamma = (const float*)d_in[8];
    const float* beta  = (const float*)d_in[9];
    const float* Wf    = (const float*)d_in[10];
    const float* bf    = (const float*)d_in[11];
    float* out = (float*)d_out;

    const int N = in_sizes[0] / 128;
    const int E = in_sizes[1] / 2;
    const int* src = ei;
    const int* dst = ei + E;

    float *px, *y, *t, *hcat, *pz, *wc, *cbias, *dis;
    int *deg, *rp, *cur, *col, *bsum;
    cudaGetSymbolAddress((void**)&px,    g_px);
    cudaGetSymbolAddress((void**)&y,     g_y);
    cudaGetSymbolAddress((void**)&t,     g_t);
    cudaGetSymbolAddress((void**)&hcat,  g_hcat);
    cudaGetSymbolAddress((void**)&pz,    g_pz);
    cudaGetSymbolAddress((void**)&wc,    g_wc);
    cudaGetSymbolAddress((void**)&cbias, g_cbias);
    cudaGetSymbolAddress((void**)&dis,   g_dis);
    cudaGetSymbolAddress((void**)&deg,   g_deg);
    cudaGetSymbolAddress((void**)&rp,    g_rowptr);
    cudaGetSymbolAddress((void**)&cur,   g_cursor);
    cudaGetSymbolAddress((void**)&col,   g_col);
    cudaGetSymbolAddress((void**)&bsum,  g_bsum);

    const int TB = 256;
    int nB = (N + TB - 1) / TB;
    int eB = (E + TB - 1) / TB;
    int nbScan = (N + SCAN_B - 1) / SCAN_B;
    int aggB = (N * 32 + TB - 1) / TB;   // warp per node, 8 nodes/block
    int gB = (N + 127) / 128;

    // --- graph prep ---
    zero_kernel<<<nB, TB>>>(deg, cur, N);
    count_kernel<<<eB, TB>>>(dst, deg, E);
    dis_kernel<<<nB, TB>>>(deg, dis, N);
    scan1_kernel<<<nbScan, SCAN_B>>>(deg, rp, bsum, N);
    scan2_kernel<<<1, 32>>>(bsum, nbScan);
    scan3_kernel<<<nB, TB>>>(rp, bsum, N);
    fill_kernel<<<eB, TB>>>(src, dst, rp, cur, col, E);

    // --- folded weights ---
    wc_kernel<<<384, 64>>>(W2, Wf, wc);
    cbias_kernel<<<1, 64>>>(b2, Wf, bf, cbias);

    // --- shared layer-0 aggregation: y = A_hat x ---
    prescale_kernel<<<(N * 32 + TB - 1) / TB, TB>>>((const float4*)x, dis, (float4*)px, N * 32);
    agg128_kernel<<<aggB, TB>>>((const float4*)px, dis, rp, deg, col, (float4*)y, N);

    // --- per-scale ---
    for (int s = 0; s < 3; s++) {
        // ph = dis * LN(relu(y @ W0_s + b0_s))
        gemm_kernel<128, 128, 0><<<gB, 256>>>(y, W0 + s * 128 * 128, dis,
                                              b0 + s * 128,
                                              gamma + (s * 3 + 0) * 128,
                                              beta + (s * 3 + 0) * 128,
                                              px, 128, 0, N);
        // t = A_hat h_s
        agg128_kernel<<<aggB, TB>>>((const float4*)px, dis, rp, deg, col, (float4*)t, N);
        // u_s = LN(relu(t @ W1_s + b1_s)) -> hcat[:, 128s:128s+128]
        gemm_kernel<128, 128, 1><<<gB, 256>>>(t, W1 + s * 128 * 128, dis,
                                              b1 + s * 128,
                                              gamma + (s * 3 + 1) * 128,
                                              beta + (s * 3 + 1) * 128,
                                              hcat, 384, s * 128, N);
    }

    // --- folded tail: pz = dis * (hcat @ Wc); out = A_hat-part + cbias ---
    gemm_kernel<384, 64, 2><<<gB, 256>>>(hcat, wc, dis, nullptr, nullptr, nullptr,
                                         pz, 64, 0, N);
    agg64_kernel<<<aggB, TB>>>((const float2*)pz, dis, rp, deg, col, cbias,
                               (float2*)out, N);
}

// round 4
// speedup vs baseline: 2.2461x; 1.2712x over previous
#include <cuda_runtime.h>
#include <cuda_bf16.h>
#include <cstdint>

#define NN 100000
#define EE 3200000
#define SCAN_B 512
#define NBLK_SCAN ((NN + SCAN_B - 1) / SCAN_B)

// -------- device scratch (no cudaMalloc allowed) --------
__device__ float g_px[NN * 128];
__device__ float g_y[NN * 128];
__device__ float g_t[NN * 128];
__device__ float g_hcat[NN * 384];
__device__ float g_pz[NN * 64];
__device__ float g_wc[384 * 64];
__device__ float g_cbias[64];
__device__ float g_dis[NN];
__device__ int   g_deg[NN];
__device__ int   g_rowptr[NN];
__device__ int   g_cursor[NN];
__device__ int   g_col[EE];
__device__ int   g_bsum[NBLK_SCAN + 1];

// ---------------------------------------------------------------------------
// graph prep
// ---------------------------------------------------------------------------
__global__ void zero_kernel(int* deg, int* cur, int n) {
    int i = blockIdx.x * blockDim.x + threadIdx.x;
    if (i < n) { deg[i] = 0; cur[i] = 0; }
}

__global__ void count_kernel(const int* __restrict__ dst, int* __restrict__ deg, int e) {
    int i = blockIdx.x * blockDim.x + threadIdx.x;
    if (i < e) atomicAdd(&deg[dst[i]], 1);
}

__global__ void dis_kernel(const int* __restrict__ deg, float* __restrict__ dis, int n) {
    int i = blockIdx.x * blockDim.x + threadIdx.x;
    if (i < n) dis[i] = rsqrtf((float)deg[i] + 1.0f);
}

__global__ void scan1_kernel(const int* __restrict__ deg, int* __restrict__ out,
                             int* __restrict__ bsum, int n) {
    __shared__ int sh[SCAN_B];
    int tid = threadIdx.x;
    int i = blockIdx.x * SCAN_B + tid;
    int v = (i < n) ? deg[i] : 0;
    sh[tid] = v;
    __syncthreads();
#pragma unroll
    for (int off = 1; off < SCAN_B; off <<= 1) {
        int t = (tid >= off) ? sh[tid - off] : 0;
        __syncthreads();
        sh[tid] += t;
        __syncthreads();
    }
    if (i < n) out[i] = sh[tid] - v;
    if (tid == SCAN_B - 1) bsum[blockIdx.x] = sh[tid];
}

__global__ void scan2_kernel(int* bsum, int nb) {
    if (threadIdx.x == 0 && blockIdx.x == 0) {
        int acc = 0;
        for (int i = 0; i < nb; i++) { int t = bsum[i]; bsum[i] = acc; acc += t; }
    }
}

__global__ void scan3_kernel(int* __restrict__ out, const int* __restrict__ bsum, int n) {
    int i = blockIdx.x * blockDim.x + threadIdx.x;
    if (i < n) out[i] += bsum[i / SCAN_B];
}

__global__ void fill_kernel(const int* __restrict__ src, const int* __restrict__ dst,
                            const int* __restrict__ rowptr, int* __restrict__ cur,
                            int* __restrict__ col, int e) {
    int i = blockIdx.x * blockDim.x + threadIdx.x;
    if (i < e) {
        int d = dst[i];
        int pos = rowptr[d] + atomicAdd(&cur[d], 1);
        col[pos] = src[i];
    }
}

// ---------------------------------------------------------------------------
// weight folding + prescale
// ---------------------------------------------------------------------------
__global__ void wc_kernel(const float* __restrict__ W2, const float* __restrict__ Wf,
                          float* __restrict__ Wc) {
    int r = blockIdx.x;
    int s = r >> 7, i = r & 127;
    int j = threadIdx.x;
    float acc = 0.0f;
#pragma unroll 8
    for (int k = 0; k < 64; k++)
        acc = fmaf(W2[(s * 128 + i) * 64 + k], Wf[(s * 64 + k) * 64 + j], acc);
    Wc[r * 64 + j] = acc;
}

__global__ void cbias_kernel(const float* __restrict__ b2, const float* __restrict__ Wf,
                             const float* __restrict__ bf, float* __restrict__ cb) {
    int j = threadIdx.x;
    float acc = bf[j];
#pragma unroll 8
    for (int r = 0; r < 192; r++) acc = fmaf(b2[r], Wf[r * 64 + j], acc);
    cb[j] = acc;
}

__global__ void prescale_kernel(const float4* __restrict__ x, const float* __restrict__ dis,
                                float4* __restrict__ px, int n4) {
    int i = blockIdx.x * blockDim.x + threadIdx.x;
    if (i < n4) {
        float s = dis[i >> 5];
        float4 v = x[i];
        v.x *= s; v.y *= s; v.z *= s; v.w *= s;
        px[i] = v;
    }
}

// ---------------------------------------------------------------------------
// mma.sync bf16 GEMM (tensor cores via baseline PTX -- no sm_103a features)
// C[nrows,BN] = epilogue( A[nrows,KDIM] @ W[KDIM,BN] )
// 2-term bf16 split: D = Ah@Bh + Al@Bh + Ah@Bl  (fp32 register accumulate)
// EPI 0: LN(relu(acc+bias)) * dis[row]
// EPI 1: LN(relu(acc+bias))
// EPI 2: acc * dis[row]          (tail; no LN, direct frag store)
// ---------------------------------------------------------------------------
__device__ __forceinline__ uint32_t smem_u32(const void* p) {
    uint32_t a;
    asm("{ .reg .u64 t; cvta.to.shared.u64 t, %1; cvt.u32.u64 %0, t; }"
        : "=r"(a) : "l"(p));
    return a;
}

#define LDSM_X4(r, addr)                                                      \
    asm volatile("ldmatrix.sync.aligned.m8n8.x4.shared.b16 {%0,%1,%2,%3}, [%4];" \
                 : "=r"((r)[0]), "=r"((r)[1]), "=r"((r)[2]), "=r"((r)[3])     \
                 : "r"(addr))

#define LDSM_X2T(r, addr)                                                     \
    asm volatile("ldmatrix.sync.aligned.m8n8.x2.trans.shared.b16 {%0,%1}, [%2];" \
                 : "=r"((r)[0]), "=r"((r)[1]) : "r"(addr))

#define MMA_BF16(d, a, b)                                                     \
    asm volatile("mma.sync.aligned.m16n8k16.row.col.f32.bf16.bf16.f32 "       \
                 "{%0,%1,%2,%3}, {%4,%5,%6,%7}, {%8,%9}, {%0,%1,%2,%3};"      \
                 : "+f"((d)[0]), "+f"((d)[1]), "+f"((d)[2]), "+f"((d)[3])     \
                 : "r"((a)[0]), "r"((a)[1]), "r"((a)[2]), "r"((a)[3]),        \
                   "r"((b)[0]), "r"((b)[1]))

template <int KDIM, int BN, int EPI>
__global__ void __launch_bounds__(256, 1)
tgemm_kernel(const float* __restrict__ A, const float* __restrict__ W,
             const float* __restrict__ dis, const float* __restrict__ bias,
             const float* __restrict__ gamma, const float* __restrict__ beta,
             float* __restrict__ C, int ldo, int coloff, int nrows) {
    constexpr int LDA = 136;            // bf16 elems per A row (+8 pad)
    constexpr int LDB = BN + 8;         // bf16 elems per B row (+8 pad)
    constexpr int WN = BN / 32;         // warps along N
    constexpr int WM = 8 / WN;          // warps along M
    constexpr int WROWS = 128 / WM;     // rows per warp
    constexpr int MI = WROWS / 16;      // m16 frags per warp
    constexpr int NJ = 4;               // n8 frags per warp (32 cols)
    constexpr int ABYTES = 128 * LDA * 2;
    constexpr int BBYTES = 128 * LDB * 2;
    // smem layout: [Ah | Al | Bh | Bl]; f32 LN buffer reuses [Ah|Al]
    constexpr int AH = 0, AL = ABYTES, BH = 2 * ABYTES, BL = BH + BBYTES;

    extern __shared__ char smem[];
    __shared__ float sh_bias[128], sh_g[128], sh_b[128];

    int tid = threadIdx.x, wid = tid >> 5, lane = tid & 31;
    int warp_m = wid % WM, warp_n = wid / WM;
    int m0 = blockIdx.x * 128;
    uint32_t sb = smem_u32(smem);

    if (EPI < 2 && tid < 128) {
        sh_bias[tid] = bias[tid];
        sh_g[tid] = gamma[tid];
        sh_b[tid] = beta[tid];
    }

    float acc[MI][NJ][4];
#pragma unroll
    for (int i = 0; i < MI; i++)
#pragma unroll
        for (int j = 0; j < NJ; j++)
#pragma unroll
            for (int k = 0; k < 4; k++) acc[i][j][k] = 0.0f;

    // per-lane ldmatrix address components
    int a_r = lane & 15, a_c8 = (lane >> 4) * 8;
    int b_r = lane & 15;

    for (int kc = 0; kc < KDIM / 128; kc++) {
        if (kc) __syncthreads();
        // ---- stage A chunk (hi/lo bf16, row-major [128][128])
#pragma unroll
        for (int it = 0; it < 32; it++) {
            int idx = it * 256 + tid;
            int row = idx >> 6, c2 = idx & 63;
            int rg = m0 + row;
            float2 a = (rg < nrows)
                ? *(const float2*)(A + (size_t)rg * KDIM + kc * 128 + c2 * 2)
                : make_float2(0.0f, 0.0f);
            __nv_bfloat162 hi, lo;
            hi.x = __float2bfloat16(a.x); hi.y = __float2bfloat16(a.y);
            lo.x = __float2bfloat16(a.x - __bfloat162float(hi.x));
            lo.y = __float2bfloat16(a.y - __bfloat162float(hi.y));
            int off = (row * LDA + c2 * 2) * 2;
            *(uint32_t*)(smem + AH + off) = *(uint32_t*)&hi;
            *(uint32_t*)(smem + AL + off) = *(uint32_t*)&lo;
        }
        // ---- stage B chunk (hi/lo bf16, [128 k][BN n])
#pragma unroll
        for (int it = 0; it < (128 * BN / 2) / 256; it++) {
            int idx = it * 256 + tid;
            int k = idx / (BN / 2), n2 = idx % (BN / 2);
            float2 w = *(const float2*)(W + (size_t)(kc * 128 + k) * BN + n2 * 2);
            __nv_bfloat162 hi, lo;
            hi.x = __float2bfloat16(w.x); hi.y = __float2bfloat16(w.y);
            lo.x = __float2bfloat16(w.x - __bfloat162float(hi.x));
            lo.y = __float2bfloat16(w.y - __bfloat162float(hi.y));
            int off = (k * LDB + n2 * 2) * 2;
            *(uint32_t*)(smem + BH + off) = *(uint32_t*)&hi;
            *(uint32_t*)(smem + BL + off) = *(uint32_t*)&lo;
        }
        __syncthreads();

        // ---- 3 accumulation passes: Ah*Bh, Al*Bh, Ah*Bl
        const uint32_t aBases[3] = {sb + AH, sb + AL, sb + AH};
        const uint32_t bBases[3] = {sb + BH, sb + BH, sb + BL};
#pragma unroll
        for (int p = 0; p < 3; p++) {
            uint32_t aB = aBases[p], bB = bBases[p];
#pragma unroll
            for (int ks = 0; ks < 8; ks++) {
                uint32_t af[MI][4], bf_[NJ][2];
#pragma unroll
                for (int mi = 0; mi < MI; mi++) {
                    uint32_t ad = aB +
                        ((warp_m * WROWS + mi * 16 + a_r) * LDA + ks * 16 + a_c8) * 2;
                    LDSM_X4(af[mi], ad);
                }
#pragma unroll
                for (int nj = 0; nj < NJ; nj++) {
                    uint32_t bd = bB +
                        ((ks * 16 + b_r) * LDB + warp_n * 32 + nj * 8) * 2;
                    LDSM_X2T(bf_[nj], bd);
                }
#pragma unroll
                for (int mi = 0; mi < MI; mi++)
#pragma unroll
                    for (int nj = 0; nj < NJ; nj++)
                        MMA_BF16(acc[mi][nj], af[mi], bf_[nj]);
            }
        }
    }

    int g = lane >> 2, q2 = (lane & 3) * 2;

    if (EPI == 2) {
        // direct store: C[r, n] = acc * dis[r]
#pragma unroll
        for (int mi = 0; mi < MI; mi++) {
#pragma unroll
            for (int nj = 0; nj < NJ; nj++) {
                int n = warp_n * 32 + nj * 8 + q2;
                int r0 = m0 + warp_m * WROWS + mi * 16 + g;
                if (r0 < nrows) {
                    float s = dis[r0];
                    float2 o = {acc[mi][nj][0] * s, acc[mi][nj][1] * s};
                    *(float2*)(C + (size_t)r0 * BN + n) = o;
                }
                int r1 = r0 + 8;
                if (r1 < nrows) {
                    float s = dis[r1];
                    float2 o = {acc[mi][nj][2] * s, acc[mi][nj][3] * s};
                    *(float2*)(C + (size_t)r1 * BN + n) = o;
                }
            }
        }
        return;
    }

    // ---- LN epilogue via padded f32 smem buffer (reuses A region)
    __syncthreads();
    float* Cs = (float*)smem;   // [128][129]
#pragma unroll
    for (int mi = 0; mi < MI; mi++)
#pragma unroll
        for (int nj = 0; nj < NJ; nj++) {
            int rl = warp_m * WROWS + mi * 16 + g;
            int n = warp_n * 32 + nj * 8 + q2;
            Cs[rl * 129 + n]           = acc[mi][nj][0];
            Cs[rl * 129 + n + 1]       = acc[mi][nj][1];
            Cs[(rl + 8) * 129 + n]     = acc[mi][nj][2];
            Cs[(rl + 8) * 129 + n + 1] = acc[mi][nj][3];
        }
    __syncthreads();

    int row = tid >> 1, half = tid & 1;
    float v[64];
    float s1 = 0.0f, s2 = 0.0f;
#pragma unroll
    for (int j = 0; j < 64; j++) {
        float t = fmaxf(Cs[row * 129 + half * 64 + j] + sh_bias[half * 64 + j], 0.0f);
        v[j] = t; s1 += t; s2 += t * t;
    }
    s1 += __shfl_xor_sync(0xffffffffu, s1, 1);
    s2 += __shfl_xor_sync(0xffffffffu, s2, 1);
    float mu = s1 * (1.0f / 128.0f);
    float var = s2 * (1.0f / 128.0f) - mu * mu;
    float inv = rsqrtf(var + 1e-5f);

    int rg = m0 + row;
    if (rg < nrows) {
        float sc = (EPI == 0) ? dis[rg] : 1.0f;
        float* outp = C + (size_t)rg * ldo + coloff + half * 64;
#pragma unroll
        for (int j = 0; j < 64; j += 4) {
            float4 o;
            o.x = ((v[j + 0] - mu) * inv * sh_g[half * 64 + j + 0] + sh_b[half * 64 + j + 0]) * sc;
            o.y = ((v[j + 1] - mu) * inv * sh_g[half * 64 + j + 1] + sh_b[half * 64 + j + 1]) * sc;
            o.z = ((v[j + 2] - mu) * inv * sh_g[half * 64 + j + 2] + sh_b[half * 64 + j + 2]) * sc;
            o.w = ((v[j + 3] - mu) * inv * sh_g[half * 64 + j + 3] + sh_b[half * 64 + j + 3]) * sc;
            *(float4*)(outp + j) = o;
        }
    }
}

// smem sizes for the instantiations
#define SMEM_128 (2 * (128 * 136 * 2) + 2 * (128 * 136 * 2))   // 139264
#define SMEM_64  (2 * (128 * 136 * 2) + 2 * (128 * 72 * 2))    // 106496

// ---------------------------------------------------------------------------
// aggregation (warp per node)
// ---------------------------------------------------------------------------
__global__ void __launch_bounds__(256)
agg128_kernel(const float4* __restrict__ p, const float* __restrict__ dis,
              const int* __restrict__ rowptr, const int* __restrict__ deg,
              const int* __restrict__ col, float4* __restrict__ out, int n) {
    int w = (blockIdx.x * blockDim.x + threadIdx.x) >> 5;
    if (w >= n) return;
    int lane = threadIdx.x & 31;
    int start = rowptr[w], d = deg[w];
    float4 a = p[(size_t)w * 32 + lane];
    float ax = a.x, ay = a.y, az = a.z, aw = a.w;

    int c0 = 0;
    for (; c0 + 32 <= d; c0 += 32) {
        int idx = col[start + c0 + lane];
#pragma unroll 8
        for (int j = 0; j < 32; j++) {
            int u = __shfl_sync(0xffffffffu, idx, j);
            float4 v = p[(size_t)u * 32 + lane];
            ax += v.x; ay += v.y; az += v.z; aw += v.w;
        }
    }
    int m = d - c0;
    if (m > 0) {
        int idx = (lane < m) ? col[start + c0 + lane] : 0;
        for (int j = 0; j < m; j++) {
            int u = __shfl_sync(0xffffffffu, idx, j);
            float4 v = p[(size_t)u * 32 + lane];
            ax += v.x; ay += v.y; az += v.z; aw += v.w;
        }
    }
    float s = dis[w];
    float4 o = {ax * s, ay * s, az * s, aw * s};
    out[(size_t)w * 32 + lane] = o;
}

__global__ void __launch_bounds__(256)
agg64_kernel(const float2* __restrict__ p, const float* __restrict__ dis,
             const int* __restrict__ rowptr, const int* __restrict__ deg,
             const int* __restrict__ col, const float* __restrict__ cbias,
             float2* __restrict__ out, int n) {
    int w = (blockIdx.x * blockDim.x + threadIdx.x) >> 5;
    if (w >= n) return;
    int lane = threadIdx.x & 31;
    int start = rowptr[w], d = deg[w];
    float2 a = p[(size_t)w * 32 + lane];
    float ax = a.x, ay = a.y;

    int c0 = 0;
    for (; c0 + 32 <= d; c0 += 32) {
        int idx = col[start + c0 + lane];
#pragma unroll 8
        for (int j = 0; j < 32; j++) {
            int u = __shfl_sync(0xffffffffu, idx, j);
            float2 v = p[(size_t)u * 32 + lane];
            ax += v.x; ay += v.y;
        }
    }
    int m = d - c0;
    if (m > 0) {
        int idx = (lane < m) ? col[start + c0 + lane] : 0;
        for (int j = 0; j < m; j++) {
            int u = __shfl_sync(0xffffffffu, idx, j);
            float2 v = p[(size_t)u * 32 + lane];
            ax += v.x; ay += v.y;
        }
    }
    float s = dis[w];
    float2 o = {ax * s + cbias[lane * 2], ay * s + cbias[lane * 2 + 1]};
    out[(size_t)w * 32 + lane] = o;
}

// ---------------------------------------------------------------------------
extern "C" void kernel_launch(void* const* d_in, const int* in_sizes, int n_in,
                              void* d_out, int out_size) {
    const float* x     = (const float*)d_in[0];
    const int*   ei    = (const int*)d_in[1];
    const float* W0    = (const float*)d_in[2];
    const float* b0    = (const float*)d_in[3];
    const float* W1    = (const float*)d_in[4];
    const float* b1    = (const float*)d_in[5];
    const float* W2    = (const float*)d_in[6];
    const float* b2    = (const float*)d_in[7];
    const float* gamma = (const float*)d_in[8];
    const float* beta  = (const float*)d_in[9];
    const float* Wf    = (const float*)d_in[10];
    const float* bf    = (const float*)d_in[11];
    float* out = (float*)d_out;

    const int N = in_sizes[0] / 128;
    const int E = in_sizes[1] / 2;
    const int* src = ei;
    const int* dst = ei + E;

    float *px, *y, *t, *hcat, *pz, *wc, *cbias, *dis;
    int *deg, *rp, *cur, *col, *bsum;
    cudaGetSymbolAddress((void**)&px,    g_px);
    cudaGetSymbolAddress((void**)&y,     g_y);
    cudaGetSymbolAddress((void**)&t,     g_t);
    cudaGetSymbolAddress((void**)&hcat,  g_hcat);
    cudaGetSymbolAddress((void**)&pz,    g_pz);
    cudaGetSymbolAddress((void**)&wc,    g_wc);
    cudaGetSymbolAddress((void**)&cbias, g_cbias);
    cudaGetSymbolAddress((void**)&dis,   g_dis);
    cudaGetSymbolAddress((void**)&deg,   g_deg);
    cudaGetSymbolAddress((void**)&rp,    g_rowptr);
    cudaGetSymbolAddress((void**)&cur,   g_cursor);
    cudaGetSymbolAddress((void**)&col,   g_col);
    cudaGetSymbolAddress((void**)&bsum,  g_bsum);

    cudaFuncSetAttribute(tgemm_kernel<128, 128, 0>,
                         cudaFuncAttributeMaxDynamicSharedMemorySize, SMEM_128);
    cudaFuncSetAttribute(tgemm_kernel<128, 128, 1>,
                         cudaFuncAttributeMaxDynamicSharedMemorySize, SMEM_128);
    cudaFuncSetAttribute(tgemm_kernel<384, 64, 2>,
                         cudaFuncAttributeMaxDynamicSharedMemorySize, SMEM_64);

    const int TB = 256;
    int nB = (N + TB - 1) / TB;
    int eB = (E + TB - 1) / TB;
    int nbScan = (N + SCAN_B - 1) / SCAN_B;
    int aggB = (N * 32 + TB - 1) / TB;
    int gB = (N + 127) / 128;

    // --- graph prep ---
    zero_kernel<<<nB, TB>>>(deg, cur, N);
    count_kernel<<<eB, TB>>>(dst, deg, E);
    dis_kernel<<<nB, TB>>>(deg, dis, N);
    scan1_kernel<<<nbScan, SCAN_B>>>(deg, rp, bsum, N);
    scan2_kernel<<<1, 32>>>(bsum, nbScan);
    scan3_kernel<<<nB, TB>>>(rp, bsum, N);
    fill_kernel<<<eB, TB>>>(src, dst, rp, cur, col, E);

    // --- folded weights ---
    wc_kernel<<<384, 64>>>(W2, Wf, wc);
    cbias_kernel<<<1, 64>>>(b2, Wf, bf, cbias);

    // --- shared layer-0 aggregation: y = A_hat x ---
    prescale_kernel<<<(N * 32 + TB - 1) / TB, TB>>>((const float4*)x, dis, (float4*)px, N * 32);
    agg128_kernel<<<aggB, TB>>>((const float4*)px, dis, rp, deg, col, (float4*)y, N);

    // --- per-scale ---
    for (int s = 0; s < 3; s++) {
        tgemm_kernel<128, 128, 0><<<gB, 256, SMEM_128>>>(
            y, W0 + s * 128 * 128, dis, b0 + s * 128,
            gamma + (s * 3 + 0) * 128, beta + (s * 3 + 0) * 128,
            px, 128, 0, N);
        agg128_kernel<<<aggB, TB>>>((const float4*)px, dis, rp, deg, col, (float4*)t, N);
        tgemm_kernel<128, 128, 1><<<gB, 256, SMEM_128>>>(
            t, W1 + s * 128 * 128, dis, b1 + s * 128,
            gamma + (s * 3 + 1) * 128, beta + (s * 3 + 1) * 128,
            hcat, 384, s * 128, N);
    }

    // --- folded tail: pz = dis * (hcat @ Wc); out = agg + cbias ---
    tgemm_kernel<384, 64, 2><<<gB, 256, SMEM_64>>>(
        hcat, wc, dis, nullptr, nullptr, nullptr, pz, 64, 0, N);
    agg64_kernel<<<aggB, TB>>>((const float2*)pz, dis, rp, deg, col, cbias,
                               (float2*)out, N);
}

// round 5
// speedup vs baseline: 2.6709x; 1.1891x over previous
#include <cuda_runtime.h>
#include <cuda_bf16.h>
#include <cuda_fp16.h>
#include <cstdint>

#define NN 100000
#define EE 3200000
#define SCAN_B 512
#define NBLK_SCAN ((NN + SCAN_B - 1) / SCAN_B)

// -------- device scratch (no cudaMalloc allowed) --------
__device__ float  g_px[NN * 128];        // fp32 prescaled x
__device__ float  g_y[NN * 128];         // y = A_hat x
__device__ __half g_ph[3][NN * 128];     // per-scale dis*LN(relu(...)) in fp16
__device__ float  g_ts[3][NN * 128];     // per-scale t_s = A_hat ph_s
__device__ float  g_hcat[NN * 384];
__device__ float  g_pz[NN * 64];
__device__ float  g_wc[384 * 64];
__device__ float  g_cbias[64];
__device__ float  g_dis[NN];
__device__ int    g_deg[NN];
__device__ int    g_rowptr[NN];
__device__ int    g_cursor[NN];
__device__ int    g_col[EE];
__device__ int    g_bsum[NBLK_SCAN + 1];

// ---------------------------------------------------------------------------
// graph prep
// ---------------------------------------------------------------------------
__global__ void zero_kernel(int* deg, int* cur, int n) {
    int i = blockIdx.x * blockDim.x + threadIdx.x;
    if (i < n) { deg[i] = 0; cur[i] = 0; }
}

__global__ void count_kernel(const int* __restrict__ dst, int* __restrict__ deg, int e) {
    int i = blockIdx.x * blockDim.x + threadIdx.x;
    if (i < e) atomicAdd(&deg[dst[i]], 1);
}

__global__ void dis_kernel(const int* __restrict__ deg, float* __restrict__ dis, int n) {
    int i = blockIdx.x * blockDim.x + threadIdx.x;
    if (i < n) dis[i] = rsqrtf((float)deg[i] + 1.0f);
}

__global__ void scan1_kernel(const int* __restrict__ deg, int* __restrict__ out,
                             int* __restrict__ bsum, int n) {
    __shared__ int sh[SCAN_B];
    int tid = threadIdx.x;
    int i = blockIdx.x * SCAN_B + tid;
    int v = (i < n) ? deg[i] : 0;
    sh[tid] = v;
    __syncthreads();
#pragma unroll
    for (int off = 1; off < SCAN_B; off <<= 1) {
        int t = (tid >= off) ? sh[tid - off] : 0;
        __syncthreads();
        sh[tid] += t;
        __syncthreads();
    }
    if (i < n) out[i] = sh[tid] - v;
    if (tid == SCAN_B - 1) bsum[blockIdx.x] = sh[tid];
}

__global__ void scan2_kernel(int* bsum, int nb) {
    if (threadIdx.x == 0 && blockIdx.x == 0) {
        int acc = 0;
        for (int i = 0; i < nb; i++) { int t = bsum[i]; bsum[i] = acc; acc += t; }
    }
}

__global__ void scan3_kernel(int* __restrict__ out, const int* __restrict__ bsum, int n) {
    int i = blockIdx.x * blockDim.x + threadIdx.x;
    if (i < n) out[i] += bsum[i / SCAN_B];
}

__global__ void fill_kernel(const int* __restrict__ src, const int* __restrict__ dst,
                            const int* __restrict__ rowptr, int* __restrict__ cur,
                            int* __restrict__ col, int e) {
    int i = blockIdx.x * blockDim.x + threadIdx.x;
    if (i < e) {
        int d = dst[i];
        int pos = rowptr[d] + atomicAdd(&cur[d], 1);
        col[pos] = src[i];
    }
}

// ---------------------------------------------------------------------------
// weight folding + prescale
// ---------------------------------------------------------------------------
__global__ void wc_kernel(const float* __restrict__ W2, const float* __restrict__ Wf,
                          float* __restrict__ Wc) {
    int r = blockIdx.x;
    int s = r >> 7, i = r & 127;
    int j = threadIdx.x;
    float acc = 0.0f;
#pragma unroll 8
    for (int k = 0; k < 64; k++)
        acc = fmaf(W2[(s * 128 + i) * 64 + k], Wf[(s * 64 + k) * 64 + j], acc);
    Wc[r * 64 + j] = acc;
}

__global__ void cbias_kernel(const float* __restrict__ b2, const float* __restrict__ Wf,
                             const float* __restrict__ bf, float* __restrict__ cb) {
    int j = threadIdx.x;
    float acc = bf[j];
#pragma unroll 8
    for (int r = 0; r < 192; r++) acc = fmaf(b2[r], Wf[r * 64 + j], acc);
    cb[j] = acc;
}

__global__ void prescale_kernel(const float4* __restrict__ x, const float* __restrict__ dis,
                                float4* __restrict__ px, int n4) {
    int i = blockIdx.x * blockDim.x + threadIdx.x;
    if (i < n4) {
        float s = dis[i >> 5];
        float4 v = x[i];
        v.x *= s; v.y *= s; v.z *= s; v.w *= s;
        px[i] = v;
    }
}

// ---------------------------------------------------------------------------
// mma.sync bf16 GEMM (baseline PTX tensor cores)
// 2-term bf16 split: D = Ah@Bh + Al@Bh + Ah@Bl
// EPI 1: LN(relu(acc+bias))                      -> fp32 C (ld=ldo, coloff)
// EPI 2: acc * dis[row]                           -> fp32 C
// EPI 3: LN(relu(acc+bias)) * dis[row]            -> FP16 C (row stride 128)
// ---------------------------------------------------------------------------
__device__ __forceinline__ uint32_t smem_u32(const void* p) {
    uint32_t a;
    asm("{ .reg .u64 t; cvta.to.shared.u64 t, %1; cvt.u32.u64 %0, t; }"
        : "=r"(a) : "l"(p));
    return a;
}

#define LDSM_X4(r, addr)                                                      \
    asm volatile("ldmatrix.sync.aligned.m8n8.x4.shared.b16 {%0,%1,%2,%3}, [%4];" \
                 : "=r"((r)[0]), "=r"((r)[1]), "=r"((r)[2]), "=r"((r)[3])     \
                 : "r"(addr))

#define LDSM_X2T(r, addr)                                                     \
    asm volatile("ldmatrix.sync.aligned.m8n8.x2.trans.shared.b16 {%0,%1}, [%2];" \
                 : "=r"((r)[0]), "=r"((r)[1]) : "r"(addr))

#define MMA_BF16(d, a, b)                                                     \
    asm volatile("mma.sync.aligned.m16n8k16.row.col.f32.bf16.bf16.f32 "       \
                 "{%0,%1,%2,%3}, {%4,%5,%6,%7}, {%8,%9}, {%0,%1,%2,%3};"      \
                 : "+f"((d)[0]), "+f"((d)[1]), "+f"((d)[2]), "+f"((d)[3])     \
                 : "r"((a)[0]), "r"((a)[1]), "r"((a)[2]), "r"((a)[3]),        \
                   "r"((b)[0]), "r"((b)[1]))

template <int KDIM, int BN, int EPI>
__global__ void __launch_bounds__(256, 1)
tgemm_kernel(const float* __restrict__ A, const float* __restrict__ W,
             const float* __restrict__ dis, const float* __restrict__ bias,
             const float* __restrict__ gamma, const float* __restrict__ beta,
             float* __restrict__ C, int ldo, int coloff, int nrows) {
    constexpr int LDA = 136;
    constexpr int LDB = BN + 8;
    constexpr int WN = BN / 32;
    constexpr int WM = 8 / WN;
    constexpr int WROWS = 128 / WM;
    constexpr int MI = WROWS / 16;
    constexpr int NJ = 4;
    constexpr int ABYTES = 128 * LDA * 2;
    constexpr int BBYTES = 128 * LDB * 2;
    constexpr int AH = 0, AL = ABYTES, BH = 2 * ABYTES, BL = BH + BBYTES;

    extern __shared__ char smem[];
    __shared__ float sh_bias[128], sh_g[128], sh_b[128];

    int tid = threadIdx.x, wid = tid >> 5, lane = tid & 31;
    int warp_m = wid % WM, warp_n = wid / WM;
    int m0 = blockIdx.x * 128;
    uint32_t sb = smem_u32(smem);

    if (EPI != 2 && tid < 128) {
        sh_bias[tid] = bias[tid];
        sh_g[tid] = gamma[tid];
        sh_b[tid] = beta[tid];
    }

    float acc[MI][NJ][4];
#pragma unroll
    for (int i = 0; i < MI; i++)
#pragma unroll
        for (int j = 0; j < NJ; j++)
#pragma unroll
            for (int k = 0; k < 4; k++) acc[i][j][k] = 0.0f;

    int a_r = lane & 15, a_c8 = (lane >> 4) * 8;
    int b_r = lane & 15;

    for (int kc = 0; kc < KDIM / 128; kc++) {
        if (kc) __syncthreads();
#pragma unroll
        for (int it = 0; it < 32; it++) {
            int idx = it * 256 + tid;
            int row = idx >> 6, c2 = idx & 63;
            int rg = m0 + row;
            float2 a = (rg < nrows)
                ? *(const float2*)(A + (size_t)rg * KDIM + kc * 128 + c2 * 2)
                : make_float2(0.0f, 0.0f);
            __nv_bfloat162 hi, lo;
            hi.x = __float2bfloat16(a.x); hi.y = __float2bfloat16(a.y);
            lo.x = __float2bfloat16(a.x - __bfloat162float(hi.x));
            lo.y = __float2bfloat16(a.y - __bfloat162float(hi.y));
            int off = (row * LDA + c2 * 2) * 2;
            *(uint32_t*)(smem + AH + off) = *(uint32_t*)&hi;
            *(uint32_t*)(smem + AL + off) = *(uint32_t*)&lo;
        }
#pragma unroll
        for (int it = 0; it < (128 * BN / 2) / 256; it++) {
            int idx = it * 256 + tid;
            int k = idx / (BN / 2), n2 = idx % (BN / 2);
            float2 w = *(const float2*)(W + (size_t)(kc * 128 + k) * BN + n2 * 2);
            __nv_bfloat162 hi, lo;
            hi.x = __float2bfloat16(w.x); hi.y = __float2bfloat16(w.y);
            lo.x = __float2bfloat16(w.x - __bfloat162float(hi.x));
            lo.y = __float2bfloat16(w.y - __bfloat162float(hi.y));
            int off = (k * LDB + n2 * 2) * 2;
            *(uint32_t*)(smem + BH + off) = *(uint32_t*)&hi;
            *(uint32_t*)(smem + BL + off) = *(uint32_t*)&lo;
        }
        __syncthreads();

        const uint32_t aBases[3] = {sb + AH, sb + AL, sb + AH};
        const uint32_t bBases[3] = {sb + BH, sb + BH, sb + BL};
#pragma unroll
        for (int p = 0; p < 3; p++) {
            uint32_t aB = aBases[p], bB = bBases[p];
#pragma unroll
            for (int ks = 0; ks < 8; ks++) {
                uint32_t af[MI][4], bf_[NJ][2];
#pragma unroll
                for (int mi = 0; mi < MI; mi++) {
                    uint32_t ad = aB +
                        ((warp_m * WROWS + mi * 16 + a_r) * LDA + ks * 16 + a_c8) * 2;
                    LDSM_X4(af[mi], ad);
                }
#pragma unroll
                for (int nj = 0; nj < NJ; nj++) {
                    uint32_t bd = bB +
                        ((ks * 16 + b_r) * LDB + warp_n * 32 + nj * 8) * 2;
                    LDSM_X2T(bf_[nj], bd);
                }
#pragma unroll
                for (int mi = 0; mi < MI; mi++)
#pragma unroll
                    for (int nj = 0; nj < NJ; nj++)
                        MMA_BF16(acc[mi][nj], af[mi], bf_[nj]);
            }
        }
    }

    int g = lane >> 2, q2 = (lane & 3) * 2;

    if (EPI == 2) {
#pragma unroll
        for (int mi = 0; mi < MI; mi++) {
#pragma unroll
            for (int nj = 0; nj < NJ; nj++) {
                int n = warp_n * 32 + nj * 8 + q2;
                int r0 = m0 + warp_m * WROWS + mi * 16 + g;
                if (r0 < nrows) {
                    float s = dis[r0];
                    float2 o = {acc[mi][nj][0] * s, acc[mi][nj][1] * s};
                    *(float2*)(C + (size_t)r0 * BN + n) = o;
                }
                int r1 = r0 + 8;
                if (r1 < nrows) {
                    float s = dis[r1];
                    float2 o = {acc[mi][nj][2] * s, acc[mi][nj][3] * s};
                    *(float2*)(C + (size_t)r1 * BN + n) = o;
                }
            }
        }
        return;
    }

    // LN epilogue via padded f32 smem (reuses A region)
    __syncthreads();
    float* Cs = (float*)smem;   // [128][129]
#pragma unroll
    for (int mi = 0; mi < MI; mi++)
#pragma unroll
        for (int nj = 0; nj < NJ; nj++) {
            int rl = warp_m * WROWS + mi * 16 + g;
            int n = warp_n * 32 + nj * 8 + q2;
            Cs[rl * 129 + n]           = acc[mi][nj][0];
            Cs[rl * 129 + n + 1]       = acc[mi][nj][1];
            Cs[(rl + 8) * 129 + n]     = acc[mi][nj][2];
            Cs[(rl + 8) * 129 + n + 1] = acc[mi][nj][3];
        }
    __syncthreads();

    int row = tid >> 1, half = tid & 1;
    float v[64];
    float s1 = 0.0f, s2 = 0.0f;
#pragma unroll
    for (int j = 0; j < 64; j++) {
        float t = fmaxf(Cs[row * 129 + half * 64 + j] + sh_bias[half * 64 + j], 0.0f);
        v[j] = t; s1 += t; s2 += t * t;
    }
    s1 += __shfl_xor_sync(0xffffffffu, s1, 1);
    s2 += __shfl_xor_sync(0xffffffffu, s2, 1);
    float mu = s1 * (1.0f / 128.0f);
    float var = s2 * (1.0f / 128.0f) - mu * mu;
    float inv = rsqrtf(var + 1e-5f);

    int rg = m0 + row;
    if (rg >= nrows) return;

    if (EPI == 3) {
        float sc = dis[rg];
        __half* outp = (__half*)C + (size_t)rg * 128 + half * 64;
#pragma unroll
        for (int j = 0; j < 64; j += 8) {
            float o[8];
#pragma unroll
            for (int q = 0; q < 8; q++)
                o[q] = ((v[j + q] - mu) * inv * sh_g[half * 64 + j + q]
                        + sh_b[half * 64 + j + q]) * sc;
            __half2 h0 = __floats2half2_rn(o[0], o[1]);
            __half2 h1 = __floats2half2_rn(o[2], o[3]);
            __half2 h2 = __floats2half2_rn(o[4], o[5]);
            __half2 h3 = __floats2half2_rn(o[6], o[7]);
            uint4 u;
            u.x = *(uint32_t*)&h0; u.y = *(uint32_t*)&h1;
            u.z = *(uint32_t*)&h2; u.w = *(uint32_t*)&h3;
            *(uint4*)(outp + j) = u;
        }
    } else {
        float* outp = C + (size_t)rg * ldo + coloff + half * 64;
#pragma unroll
        for (int j = 0; j < 64; j += 4) {
            float4 o;
            o.x = (v[j + 0] - mu) * inv * sh_g[half * 64 + j + 0] + sh_b[half * 64 + j + 0];
            o.y = (v[j + 1] - mu) * inv * sh_g[half * 64 + j + 1] + sh_b[half * 64 + j + 1];
            o.z = (v[j + 2] - mu) * inv * sh_g[half * 64 + j + 2] + sh_b[half * 64 + j + 2];
            o.w = (v[j + 3] - mu) * inv * sh_g[half * 64 + j + 3] + sh_b[half * 64 + j + 3];
            *(float4*)(outp + j) = o;
        }
    }
}

#define SMEM_128 (2 * (128 * 136 * 2) + 2 * (128 * 136 * 2))
#define SMEM_64  (2 * (128 * 136 * 2) + 2 * (128 * 72 * 2))

// ---------------------------------------------------------------------------
// aggregation (warp per node)
// ---------------------------------------------------------------------------
__global__ void __launch_bounds__(256)
agg128_kernel(const float4* __restrict__ p, const float* __restrict__ dis,
              const int* __restrict__ rowptr, const int* __restrict__ deg,
              const int* __restrict__ col, float4* __restrict__ out, int n) {
    int w = (blockIdx.x * blockDim.x + threadIdx.x) >> 5;
    if (w >= n) return;
    int lane = threadIdx.x & 31;
    int start = rowptr[w], d = deg[w];
    float4 a = p[(size_t)w * 32 + lane];
    float ax = a.x, ay = a.y, az = a.z, aw = a.w;

    int c0 = 0;
    for (; c0 + 32 <= d; c0 += 32) {
        int idx = col[start + c0 + lane];
#pragma unroll 8
        for (int j = 0; j < 32; j++) {
            int u = __shfl_sync(0xffffffffu, idx, j);
            float4 v = p[(size_t)u * 32 + lane];
            ax += v.x; ay += v.y; az += v.z; aw += v.w;
        }
    }
    int m = d - c0;
    if (m > 0) {
        int idx = (lane < m) ? col[start + c0 + lane] : 0;
        for (int j = 0; j < m; j++) {
            int u = __shfl_sync(0xffffffffu, idx, j);
            float4 v = p[(size_t)u * 32 + lane];
            ax += v.x; ay += v.y; az += v.z; aw += v.w;
        }
    }
    float s = dis[w];
    float4 o = {ax * s, ay * s, az * s, aw * s};
    out[(size_t)w * 32 + lane] = o;
}

// fp16 payload variant: p rows are 128 halves (256B); lane covers cols [4*lane,4*lane+4)
__global__ void __launch_bounds__(256)
agg128h_kernel(const __half* __restrict__ p, const float* __restrict__ dis,
               const int* __restrict__ rowptr, const int* __restrict__ deg,
               const int* __restrict__ col, float* __restrict__ out, int n) {
    int w = (blockIdx.x * blockDim.x + threadIdx.x) >> 5;
    if (w >= n) return;
    int lane = threadIdx.x & 31;
    const uint2* p2 = (const uint2*)p;
    int start = rowptr[w], d = deg[w];
    uint2 a = p2[(size_t)w * 32 + lane];
    float2 f0 = __half22float2(*(__half2*)&a.x);
    float2 f1 = __half22float2(*(__half2*)&a.y);
    float ax = f0.x, ay = f0.y, az = f1.x, aw = f1.y;

    int c0 = 0;
    for (; c0 + 32 <= d; c0 += 32) {
        int idx = col[start + c0 + lane];
#pragma unroll 8
        for (int j = 0; j < 32; j++) {
            int u = __shfl_sync(0xffffffffu, idx, j);
            uint2 v = p2[(size_t)u * 32 + lane];
            float2 g0 = __half22float2(*(__half2*)&v.x);
            float2 g1 = __half22float2(*(__half2*)&v.y);
            ax += g0.x; ay += g0.y; az += g1.x; aw += g1.y;
        }
    }
    int m = d - c0;
    if (m > 0) {
        int idx = (lane < m) ? col[start + c0 + lane] : 0;
        for (int j = 0; j < m; j++) {
            int u = __shfl_sync(0xffffffffu, idx, j);
            uint2 v = p2[(size_t)u * 32 + lane];
            float2 g0 = __half22float2(*(__half2*)&v.x);
            float2 g1 = __half22float2(*(__half2*)&v.y);
            ax += g0.x; ay += g0.y; az += g1.x; aw += g1.y;
        }
    }
    float s = dis[w];
    float4 o = {ax * s, ay * s, az * s, aw * s};
    ((float4*)out)[(size_t)w * 32 + lane] = o;
}

__global__ void __launch_bounds__(256)
agg64_kernel(const float2* __restrict__ p, const float* __restrict__ dis,
             const int* __restrict__ rowptr, const int* __restrict__ deg,
             const int* __restrict__ col, const float* __restrict__ cbias,
             float2* __restrict__ out, int n) {
    int w = (blockIdx.x * blockDim.x + threadIdx.x) >> 5;
    if (w >= n) return;
    int lane = threadIdx.x & 31;
    int start = rowptr[w], d = deg[w];
    float2 a = p[(size_t)w * 32 + lane];
    float ax = a.x, ay = a.y;

    int c0 = 0;
    for (; c0 + 32 <= d; c0 += 32) {
        int idx = col[start + c0 + lane];
#pragma unroll 8
        for (int j = 0; j < 32; j++) {
            int u = __shfl_sync(0xffffffffu, idx, j);
            float2 v = p[(size_t)u * 32 + lane];
            ax += v.x; ay += v.y;
        }
    }
    int m = d - c0;
    if (m > 0) {
        int idx = (lane < m) ? col[start + c0 + lane] : 0;
        for (int j = 0; j < m; j++) {
            int u = __shfl_sync(0xffffffffu, idx, j);
            float2 v = p[(size_t)u * 32 + lane];
            ax += v.x; ay += v.y;
        }
    }
    float s = dis[w];
    float2 o = {ax * s + cbias[lane * 2], ay * s + cbias[lane * 2 + 1]};
    out[(size_t)w * 32 + lane] = o;
}

// ---------------------------------------------------------------------------
extern "C" void kernel_launch(void* const* d_in, const int* in_sizes, int n_in,
                              void* d_out, int out_size) {
    const float* x     = (const float*)d_in[0];
    const int*   ei    = (const int*)d_in[1];
    const float* W0    = (const float*)d_in[2];
    const float* b0    = (const float*)d_in[3];
    const float* W1    = (const float*)d_in[4];
    const float* b1    = (const float*)d_in[5];
    const float* W2    = (const float*)d_in[6];
    const float* b2    = (const float*)d_in[7];
    const float* gamma = (const float*)d_in[8];
    const float* beta  = (const float*)d_in[9];
    const float* Wf    = (const float*)d_in[10];
    const float* bf    = (const float*)d_in[11];
    float* out = (float*)d_out;

    const int N = in_sizes[0] / 128;
    const int E = in_sizes[1] / 2;
    const int* src = ei;
    const int* dst = ei + E;

    float *px, *y, *hcat, *pz, *wc, *cbias, *dis;
    __half* ph;
    float* ts;
    int *deg, *rp, *cur, *col, *bsum;
    cudaGetSymbolAddress((void**)&px,    g_px);
    cudaGetSymbolAddress((void**)&y,     g_y);
    cudaGetSymbolAddress((void**)&ph,    g_ph);
    cudaGetSymbolAddress((void**)&ts,    g_ts);
    cudaGetSymbolAddress((void**)&hcat,  g_hcat);
    cudaGetSymbolAddress((void**)&pz,    g_pz);
    cudaGetSymbolAddress((void**)&wc,    g_wc);
    cudaGetSymbolAddress((void**)&cbias, g_cbias);
    cudaGetSymbolAddress((void**)&dis,   g_dis);
    cudaGetSymbolAddress((void**)&deg,   g_deg);
    cudaGetSymbolAddress((void**)&rp,    g_rowptr);
    cudaGetSymbolAddress((void**)&cur,   g_cursor);
    cudaGetSymbolAddress((void**)&col,   g_col);
    cudaGetSymbolAddress((void**)&bsum,  g_bsum);

    // one-time stream/event setup (first call is the uncaptured correctness run)
    static bool inited = false;
    static cudaStream_t st1, st2;
    static cudaEvent_t evY, ev1, ev2;
    if (!inited) {
        cudaStreamCreateWithFlags(&st1, cudaStreamNonBlocking);
        cudaStreamCreateWithFlags(&st2, cudaStreamNonBlocking);
        cudaEventCreateWithFlags(&evY, cudaEventDisableTiming);
        cudaEventCreateWithFlags(&ev1, cudaEventDisableTiming);
        cudaEventCreateWithFlags(&ev2, cudaEventDisableTiming);
        cudaFuncSetAttribute(tgemm_kernel<128, 128, 3>,
                             cudaFuncAttributeMaxDynamicSharedMemorySize, SMEM_128);
        cudaFuncSetAttribute(tgemm_kernel<128, 128, 1>,
                             cudaFuncAttributeMaxDynamicSharedMemorySize, SMEM_128);
        cudaFuncSetAttribute(tgemm_kernel<384, 64, 2>,
                             cudaFuncAttributeMaxDynamicSharedMemorySize, SMEM_64);
        inited = true;
    }

    const int TB = 256;
    int nB = (N + TB - 1) / TB;
    int eB = (E + TB - 1) / TB;
    int nbScan = (N + SCAN_B - 1) / SCAN_B;
    int aggB = (N * 32 + TB - 1) / TB;
    int gB = (N + 127) / 128;

    cudaStream_t s0 = 0;   // legacy default (captured)

    // --- graph prep (default stream) ---
    zero_kernel<<<nB, TB, 0, s0>>>(deg, cur, N);
    count_kernel<<<eB, TB, 0, s0>>>(dst, deg, E);
    dis_kernel<<<nB, TB, 0, s0>>>(deg, dis, N);
    scan1_kernel<<<nbScan, SCAN_B, 0, s0>>>(deg, rp, bsum, N);
    scan2_kernel<<<1, 32, 0, s0>>>(bsum, nbScan);
    scan3_kernel<<<nB, TB, 0, s0>>>(rp, bsum, N);
    fill_kernel<<<eB, TB, 0, s0>>>(src, dst, rp, cur, col, E);

    // --- folded weights ---
    wc_kernel<<<384, 64, 0, s0>>>(W2, Wf, wc);
    cbias_kernel<<<1, 64, 0, s0>>>(b2, Wf, bf, cbias);

    // --- shared layer-0 aggregation: y = A_hat x ---
    prescale_kernel<<<(N * 32 + TB - 1) / TB, TB, 0, s0>>>(
        (const float4*)x, dis, (float4*)px, N * 32);
    agg128_kernel<<<aggB, TB, 0, s0>>>((const float4*)px, dis, rp, deg, col,
                                       (float4*)y, N);
    cudaEventRecord(evY, s0);
    cudaStreamWaitEvent(st1, evY, 0);
    cudaStreamWaitEvent(st2, evY, 0);

    // --- per-scale chains on 3 streams ---
    cudaStream_t chain[3] = {s0, st1, st2};
    for (int s = 0; s < 3; s++) {
        cudaStream_t cs = chain[s];
        __half* ph_s = ph + (size_t)s * NN * 128;
        float* t_s = ts + (size_t)s * NN * 128;
        tgemm_kernel<128, 128, 3><<<gB, 256, SMEM_128, cs>>>(
            y, W0 + s * 128 * 128, dis, b0 + s * 128,
            gamma + (s * 3 + 0) * 128, beta + (s * 3 + 0) * 128,
            (float*)ph_s, 128, 0, N);
        agg128h_kernel<<<aggB, TB, 0, cs>>>(ph_s, dis, rp, deg, col, t_s, N);
        tgemm_kernel<128, 128, 1><<<gB, 256, SMEM_128, cs>>>(
            t_s, W1 + s * 128 * 128, dis, b1 + s * 128,
            gamma + (s * 3 + 1) * 128, beta + (s * 3 + 1) * 128,
            hcat, 384, s * 128, N);
    }
    cudaEventRecord(ev1, st1);
    cudaEventRecord(ev2, st2);
    cudaStreamWaitEvent(s0, ev1, 0);
    cudaStreamWaitEvent(s0, ev2, 0);

    // --- folded tail ---
    tgemm_kernel<384, 64, 2><<<gB, 256, SMEM_64, s0>>>(
        hcat, wc, dis, nullptr, nullptr, nullptr, pz, 64, 0, N);
    agg64_kernel<<<aggB, TB, 0, s0>>>((const float2*)pz, dis, rp, deg, col, cbias,
                                      (float2*)out, N);
}

// round 6
// speedup vs baseline: 2.8006x; 1.0486x over previous
#include <cuda_runtime.h>
#include <cuda_bf16.h>
#include <cuda_fp16.h>
#include <cstdint>

#define NN 100000
#define EE 3200000
#define SCAN_B 512
#define NBLK_SCAN ((NN + SCAN_B - 1) / SCAN_B)

// -------- device scratch (no cudaMalloc allowed) --------
__device__ __half g_pxh[NN * 128];       // fp16 dis-prescaled x
__device__ float  g_y[NN * 128];         // y = A_hat x  (fp32)
__device__ __half g_ph[3][NN * 128];     // per-scale dis*LN(relu(...)) fp16
__device__ float  g_ts[3][NN * 128];     // per-scale t_s = A_hat ph_s
__device__ float  g_hcat[NN * 384];
__device__ __half g_pzh[NN * 64];        // fp16 tail
__device__ float  g_wc[384 * 64];
__device__ float  g_cbias[64];
__device__ float  g_dis[NN];
__device__ int    g_deg[NN];
__device__ int    g_rowptr[NN];
__device__ int    g_cursor[NN];
__device__ int    g_col[EE];
__device__ int    g_bsum[NBLK_SCAN + 1];

// ---------------------------------------------------------------------------
// graph prep
// ---------------------------------------------------------------------------
__global__ void zero_kernel(int* deg, int* cur, int n) {
    int i = blockIdx.x * blockDim.x + threadIdx.x;
    if (i < n) { deg[i] = 0; cur[i] = 0; }
}

__global__ void count_kernel(const int* __restrict__ dst, int* __restrict__ deg, int e) {
    int i = blockIdx.x * blockDim.x + threadIdx.x;
    if (i < e) atomicAdd(&deg[dst[i]], 1);
}

__global__ void dis_kernel(const int* __restrict__ deg, float* __restrict__ dis, int n) {
    int i = blockIdx.x * blockDim.x + threadIdx.x;
    if (i < n) dis[i] = rsqrtf((float)deg[i] + 1.0f);
}

__global__ void scan1_kernel(const int* __restrict__ deg, int* __restrict__ out,
                             int* __restrict__ bsum, int n) {
    __shared__ int sh[SCAN_B];
    int tid = threadIdx.x;
    int i = blockIdx.x * SCAN_B + tid;
    int v = (i < n) ? deg[i] : 0;
    sh[tid] = v;
    __syncthreads();
#pragma unroll
    for (int off = 1; off < SCAN_B; off <<= 1) {
        int t = (tid >= off) ? sh[tid - off] : 0;
        __syncthreads();
        sh[tid] += t;
        __syncthreads();
    }
    if (i < n) out[i] = sh[tid] - v;
    if (tid == SCAN_B - 1) bsum[blockIdx.x] = sh[tid];
}

__global__ void scan2_kernel(int* bsum, int nb) {
    if (threadIdx.x == 0 && blockIdx.x == 0) {
        int acc = 0;
        for (int i = 0; i < nb; i++) { int t = bsum[i]; bsum[i] = acc; acc += t; }
    }
}

__global__ void scan3_kernel(int* __restrict__ out, const int* __restrict__ bsum, int n) {
    int i = blockIdx.x * blockDim.x + threadIdx.x;
    if (i < n) out[i] += bsum[i / SCAN_B];
}

__global__ void fill_kernel(const int* __restrict__ src, const int* __restrict__ dst,
                            const int* __restrict__ rowptr, int* __restrict__ cur,
                            int* __restrict__ col, int e) {
    int i = blockIdx.x * blockDim.x + threadIdx.x;
    if (i < e) {
        int d = dst[i];
        int pos = rowptr[d] + atomicAdd(&cur[d], 1);
        col[pos] = src[i];
    }
}

// ---------------------------------------------------------------------------
// weight folding + prescale
// ---------------------------------------------------------------------------
__global__ void wc_kernel(const float* __restrict__ W2, const float* __restrict__ Wf,
                          float* __restrict__ Wc) {
    int r = blockIdx.x;
    int s = r >> 7, i = r & 127;
    int j = threadIdx.x;
    float acc = 0.0f;
#pragma unroll 8
    for (int k = 0; k < 64; k++)
        acc = fmaf(W2[(s * 128 + i) * 64 + k], Wf[(s * 64 + k) * 64 + j], acc);
    Wc[r * 64 + j] = acc;
}

__global__ void cbias_kernel(const float* __restrict__ b2, const float* __restrict__ Wf,
                             const float* __restrict__ bf, float* __restrict__ cb) {
    int j = threadIdx.x;
    float acc = bf[j];
#pragma unroll 8
    for (int r = 0; r < 192; r++) acc = fmaf(b2[r], Wf[r * 64 + j], acc);
    cb[j] = acc;
}

// px_h = fp16( dis[row] * x ), 4 elems per thread
__global__ void prescale_h_kernel(const float4* __restrict__ x, const float* __restrict__ dis,
                                  uint2* __restrict__ px, int n4) {
    int i = blockIdx.x * blockDim.x + threadIdx.x;
    if (i < n4) {
        float s = dis[i >> 5];
        float4 v = x[i];
        __half2 h0 = __floats2half2_rn(v.x * s, v.y * s);
        __half2 h1 = __floats2half2_rn(v.z * s, v.w * s);
        uint2 u;
        u.x = *(uint32_t*)&h0; u.y = *(uint32_t*)&h1;
        px[i] = u;
    }
}

// ---------------------------------------------------------------------------
// mma.sync bf16 GEMM (baseline PTX tensor cores)
// 2-term bf16 split: D = Ah@Bh + Al@Bh + Ah@Bl
// EPI 1: LN(relu(acc+bias))            -> fp32 C (ld=ldo, coloff)
// EPI 2: acc * dis[row]                -> FP16 C (row stride BN)
// EPI 3: LN(relu(acc+bias)) * dis[row] -> FP16 C (row stride 128)
// ---------------------------------------------------------------------------
__device__ __forceinline__ uint32_t smem_u32(const void* p) {
    uint32_t a;
    asm("{ .reg .u64 t; cvta.to.shared.u64 t, %1; cvt.u32.u64 %0, t; }"
        : "=r"(a) : "l"(p));
    return a;
}

#define LDSM_X4(r, addr)                                                      \
    asm volatile("ldmatrix.sync.aligned.m8n8.x4.shared.b16 {%0,%1,%2,%3}, [%4];" \
                 : "=r"((r)[0]), "=r"((r)[1]), "=r"((r)[2]), "=r"((r)[3])     \
                 : "r"(addr))

#define LDSM_X2T(r, addr)                                                     \
    asm volatile("ldmatrix.sync.aligned.m8n8.x2.trans.shared.b16 {%0,%1}, [%2];" \
                 : "=r"((r)[0]), "=r"((r)[1]) : "r"(addr))

#define MMA_BF16(d, a, b)                                                     \
    asm volatile("mma.sync.aligned.m16n8k16.row.col.f32.bf16.bf16.f32 "       \
                 "{%0,%1,%2,%3}, {%4,%5,%6,%7}, {%8,%9}, {%0,%1,%2,%3};"      \
                 : "+f"((d)[0]), "+f"((d)[1]), "+f"((d)[2]), "+f"((d)[3])     \
                 : "r"((a)[0]), "r"((a)[1]), "r"((a)[2]), "r"((a)[3]),        \
                   "r"((b)[0]), "r"((b)[1]))

template <int KDIM, int BN, int EPI>
__global__ void __launch_bounds__(256, 1)
tgemm_kernel(const float* __restrict__ A, const float* __restrict__ W,
             const float* __restrict__ dis, const float* __restrict__ bias,
             const float* __restrict__ gamma, const float* __restrict__ beta,
             void* __restrict__ Cv, int ldo, int coloff, int nrows) {
    constexpr int LDA = 136;
    constexpr int LDB = BN + 8;
    constexpr int WN = BN / 32;
    constexpr int WM = 8 / WN;
    constexpr int WROWS = 128 / WM;
    constexpr int MI = WROWS / 16;
    constexpr int NJ = 4;
    constexpr int ABYTES = 128 * LDA * 2;
    constexpr int BBYTES = 128 * LDB * 2;
    constexpr int AH = 0, AL = ABYTES, BH = 2 * ABYTES, BL = BH + BBYTES;

    extern __shared__ char smem[];
    __shared__ float sh_bias[128], sh_g[128], sh_b[128];

    int tid = threadIdx.x, wid = tid >> 5, lane = tid & 31;
    int warp_m = wid % WM, warp_n = wid / WM;
    int m0 = blockIdx.x * 128;
    uint32_t sb = smem_u32(smem);

    if (EPI != 2 && tid < 128) {
        sh_bias[tid] = bias[tid];
        sh_g[tid] = gamma[tid];
        sh_b[tid] = beta[tid];
    }

    float acc[MI][NJ][4];
#pragma unroll
    for (int i = 0; i < MI; i++)
#pragma unroll
        for (int j = 0; j < NJ; j++)
#pragma unroll
            for (int k = 0; k < 4; k++) acc[i][j][k] = 0.0f;

    int a_r = lane & 15, a_c8 = (lane >> 4) * 8;
    int b_r = lane & 15;

    for (int kc = 0; kc < KDIM / 128; kc++) {
        if (kc) __syncthreads();
#pragma unroll
        for (int it = 0; it < 32; it++) {
            int idx = it * 256 + tid;
            int row = idx >> 6, c2 = idx & 63;
            int rg = m0 + row;
            float2 a = (rg < nrows)
                ? *(const float2*)(A + (size_t)rg * KDIM + kc * 128 + c2 * 2)
                : make_float2(0.0f, 0.0f);
            __nv_bfloat162 hi, lo;
            hi.x = __float2bfloat16(a.x); hi.y = __float2bfloat16(a.y);
            lo.x = __float2bfloat16(a.x - __bfloat162float(hi.x));
            lo.y = __float2bfloat16(a.y - __bfloat162float(hi.y));
            int off = (row * LDA + c2 * 2) * 2;
            *(uint32_t*)(smem + AH + off) = *(uint32_t*)&hi;
            *(uint32_t*)(smem + AL + off) = *(uint32_t*)&lo;
        }
#pragma unroll
        for (int it = 0; it < (128 * BN / 2) / 256; it++) {
            int idx = it * 256 + tid;
            int k = idx / (BN / 2), n2 = idx % (BN / 2);
            float2 w = *(const float2*)(W + (size_t)(kc * 128 + k) * BN + n2 * 2);
            __nv_bfloat162 hi, lo;
            hi.x = __float2bfloat16(w.x); hi.y = __float2bfloat16(w.y);
            lo.x = __float2bfloat16(w.x - __bfloat162float(hi.x));
            lo.y = __float2bfloat16(w.y - __bfloat162float(hi.y));
            int off = (k * LDB + n2 * 2) * 2;
            *(uint32_t*)(smem + BH + off) = *(uint32_t*)&hi;
            *(uint32_t*)(smem + BL + off) = *(uint32_t*)&lo;
        }
        __syncthreads();

        const uint32_t aBases[3] = {sb + AH, sb + AL, sb + AH};
        const uint32_t bBases[3] = {sb + BH, sb + BH, sb + BL};
#pragma unroll
        for (int p = 0; p < 3; p++) {
            uint32_t aB = aBases[p], bB = bBases[p];
#pragma unroll
            for (int ks = 0; ks < 8; ks++) {
                uint32_t af[MI][4], bf_[NJ][2];
#pragma unroll
                for (int mi = 0; mi < MI; mi++) {
                    uint32_t ad = aB +
                        ((warp_m * WROWS + mi * 16 + a_r) * LDA + ks * 16 + a_c8) * 2;
                    LDSM_X4(af[mi], ad);
                }
#pragma unroll
                for (int nj = 0; nj < NJ; nj++) {
                    uint32_t bd = bB +
                        ((ks * 16 + b_r) * LDB + warp_n * 32 + nj * 8) * 2;
                    LDSM_X2T(bf_[nj], bd);
                }
#pragma unroll
                for (int mi = 0; mi < MI; mi++)
#pragma unroll
                    for (int nj = 0; nj < NJ; nj++)
                        MMA_BF16(acc[mi][nj], af[mi], bf_[nj]);
            }
        }
    }

    int g = lane >> 2, q2 = (lane & 3) * 2;

    if (EPI == 2) {
        // fp16 store: pz[r, n] = fp16(acc * dis[r]), row stride BN halves
        __half* outp = (__half*)Cv;
#pragma unroll
        for (int mi = 0; mi < MI; mi++) {
#pragma unroll
            for (int nj = 0; nj < NJ; nj++) {
                int n = warp_n * 32 + nj * 8 + q2;
                int r0 = m0 + warp_m * WROWS + mi * 16 + g;
                if (r0 < nrows) {
                    float s = dis[r0];
                    __half2 h = __floats2half2_rn(acc[mi][nj][0] * s, acc[mi][nj][1] * s);
                    *(uint32_t*)(outp + (size_t)r0 * BN + n) = *(uint32_t*)&h;
                }
                int r1 = r0 + 8;
                if (r1 < nrows) {
                    float s = dis[r1];
                    __half2 h = __floats2half2_rn(acc[mi][nj][2] * s, acc[mi][nj][3] * s);
                    *(uint32_t*)(outp + (size_t)r1 * BN + n) = *(uint32_t*)&h;
                }
            }
        }
        return;
    }

    // LN epilogue via padded f32 smem (reuses A region)
    __syncthreads();
    float* Cs = (float*)smem;   // [128][129]
#pragma unroll
    for (int mi = 0; mi < MI; mi++)
#pragma unroll
        for (int nj = 0; nj < NJ; nj++) {
            int rl = warp_m * WROWS + mi * 16 + g;
            int n = warp_n * 32 + nj * 8 + q2;
            Cs[rl * 129 + n]           = acc[mi][nj][0];
            Cs[rl * 129 + n + 1]       = acc[mi][nj][1];
            Cs[(rl + 8) * 129 + n]     = acc[mi][nj][2];
            Cs[(rl + 8) * 129 + n + 1] = acc[mi][nj][3];
        }
    __syncthreads();

    int row = tid >> 1, half = tid & 1;
    float v[64];
    float s1 = 0.0f, s2 = 0.0f;
#pragma unroll
    for (int j = 0; j < 64; j++) {
        float t = fmaxf(Cs[row * 129 + half * 64 + j] + sh_bias[half * 64 + j], 0.0f);
        v[j] = t; s1 += t; s2 += t * t;
    }
    s1 += __shfl_xor_sync(0xffffffffu, s1, 1);
    s2 += __shfl_xor_sync(0xffffffffu, s2, 1);
    float mu = s1 * (1.0f / 128.0f);
    float var = s2 * (1.0f / 128.0f) - mu * mu;
    float inv = rsqrtf(var + 1e-5f);

    int rg = m0 + row;
    if (rg >= nrows) return;

    if (EPI == 3) {
        float sc = dis[rg];
        __half* outp = (__half*)Cv + (size_t)rg * 128 + half * 64;
#pragma unroll
        for (int j = 0; j < 64; j += 8) {
            float o[8];
#pragma unroll
            for (int q = 0; q < 8; q++)
                o[q] = ((v[j + q] - mu) * inv * sh_g[half * 64 + j + q]
                        + sh_b[half * 64 + j + q]) * sc;
            __half2 h0 = __floats2half2_rn(o[0], o[1]);
            __half2 h1 = __floats2half2_rn(o[2], o[3]);
            __half2 h2 = __floats2half2_rn(o[4], o[5]);
            __half2 h3 = __floats2half2_rn(o[6], o[7]);
            uint4 u;
            u.x = *(uint32_t*)&h0; u.y = *(uint32_t*)&h1;
            u.z = *(uint32_t*)&h2; u.w = *(uint32_t*)&h3;
            *(uint4*)(outp + j) = u;
        }
    } else {
        float* outp = (float*)Cv + (size_t)rg * ldo + coloff + half * 64;
#pragma unroll
        for (int j = 0; j < 64; j += 4) {
            float4 o;
            o.x = (v[j + 0] - mu) * inv * sh_g[half * 64 + j + 0] + sh_b[half * 64 + j + 0];
            o.y = (v[j + 1] - mu) * inv * sh_g[half * 64 + j + 1] + sh_b[half * 64 + j + 1];
            o.z = (v[j + 2] - mu) * inv * sh_g[half * 64 + j + 2] + sh_b[half * 64 + j + 2];
            o.w = (v[j + 3] - mu) * inv * sh_g[half * 64 + j + 3] + sh_b[half * 64 + j + 3];
            *(float4*)(outp + j) = o;
        }
    }
}

#define SMEM_128 (2 * (128 * 136 * 2) + 2 * (128 * 136 * 2))
#define SMEM_64  (2 * (128 * 136 * 2) + 2 * (128 * 72 * 2))

// ---------------------------------------------------------------------------
// aggregation (warp per node)
// ---------------------------------------------------------------------------
// fp16 payload, 128-wide rows (256B). out fp32.
__global__ void __launch_bounds__(256)
agg128h_kernel(const __half* __restrict__ p, const float* __restrict__ dis,
               const int* __restrict__ rowptr, const int* __restrict__ deg,
               const int* __restrict__ col, float* __restrict__ out, int n) {
    int w = (blockIdx.x * blockDim.x + threadIdx.x) >> 5;
    if (w >= n) return;
    int lane = threadIdx.x & 31;
    const uint2* p2 = (const uint2*)p;
    int start = rowptr[w], d = deg[w];
    uint2 a = p2[(size_t)w * 32 + lane];
    float2 f0 = __half22float2(*(__half2*)&a.x);
    float2 f1 = __half22float2(*(__half2*)&a.y);
    float ax = f0.x, ay = f0.y, az = f1.x, aw = f1.y;

    int c0 = 0;
    for (; c0 + 32 <= d; c0 += 32) {
        int idx = col[start + c0 + lane];
#pragma unroll 8
        for (int j = 0; j < 32; j++) {
            int u = __shfl_sync(0xffffffffu, idx, j);
            uint2 v = p2[(size_t)u * 32 + lane];
            float2 g0 = __half22float2(*(__half2*)&v.x);
            float2 g1 = __half22float2(*(__half2*)&v.y);
            ax += g0.x; ay += g0.y; az += g1.x; aw += g1.y;
        }
    }
    int m = d - c0;
    if (m > 0) {
        int idx = (lane < m) ? col[start + c0 + lane] : 0;
        for (int j = 0; j < m; j++) {
            int u = __shfl_sync(0xffffffffu, idx, j);
            uint2 v = p2[(size_t)u * 32 + lane];
            float2 g0 = __half22float2(*(__half2*)&v.x);
            float2 g1 = __half22float2(*(__half2*)&v.y);
            ax += g0.x; ay += g0.y; az += g1.x; aw += g1.y;
        }
    }
    float s = dis[w];
    float4 o = {ax * s, ay * s, az * s, aw * s};
    ((float4*)out)[(size_t)w * 32 + lane] = o;
}

// fp16 payload, 64-wide rows (128B): lane holds 2 halves. final output fp32 + cbias.
__global__ void __launch_bounds__(256)
agg64h_kernel(const uint32_t* __restrict__ p, const float* __restrict__ dis,
              const int* __restrict__ rowptr, const int* __restrict__ deg,
              const int* __restrict__ col, const float* __restrict__ cbias,
              float2* __restrict__ out, int n) {
    int w = (blockIdx.x * blockDim.x + threadIdx.x) >> 5;
    if (w >= n) return;
    int lane = threadIdx.x & 31;
    int start = rowptr[w], d = deg[w];
    uint32_t a = p[(size_t)w * 32 + lane];
    float2 f = __half22float2(*(__half2*)&a);
    float ax = f.x, ay = f.y;

    int c0 = 0;
    for (; c0 + 32 <= d; c0 += 32) {
        int idx = col[start + c0 + lane];
#pragma unroll 8
        for (int j = 0; j < 32; j++) {
            int u = __shfl_sync(0xffffffffu, idx, j);
            uint32_t v = p[(size_t)u * 32 + lane];
            float2 g = __half22float2(*(__half2*)&v);
            ax += g.x; ay += g.y;
        }
    }
    int m = d - c0;
    if (m > 0) {
        int idx = (lane < m) ? col[start + c0 + lane] : 0;
        for (int j = 0; j < m; j++) {
            int u = __shfl_sync(0xffffffffu, idx, j);
            uint32_t v = p[(size_t)u * 32 + lane];
            float2 g = __half22float2(*(__half2*)&v);
            ax += g.x; ay += g.y;
        }
    }
    float s = dis[w];
    float2 o = {ax * s + cbias[lane * 2], ay * s + cbias[lane * 2 + 1]};
    out[(size_t)w * 32 + lane] = o;
}

// ---------------------------------------------------------------------------
extern "C" void kernel_launch(void* const* d_in, const int* in_sizes, int n_in,
                              void* d_out, int out_size) {
    const float* x     = (const float*)d_in[0];
    const int*   ei    = (const int*)d_in[1];
    const float* W0    = (const float*)d_in[2];
    const float* b0    = (const float*)d_in[3];
    const float* W1    = (const float*)d_in[4];
    const float* b1    = (const float*)d_in[5];
    const float* W2    = (const float*)d_in[6];
    const float* b2    = (const float*)d_in[7];
    const float* gamma = (const float*)d_in[8];
    const float* beta  = (const float*)d_in[9];
    const float* Wf    = (const float*)d_in[10];
    const float* bf    = (const float*)d_in[11];
    float* out = (float*)d_out;

    const int N = in_sizes[0] / 128;
    const int E = in_sizes[1] / 2;
    const int* src = ei;
    const int* dst = ei + E;

    __half *pxh, *ph, *pzh;
    float *y, *ts, *hcat, *wc, *cbias, *dis;
    int *deg, *rp, *cur, *col, *bsum;
    cudaGetSymbolAddress((void**)&pxh,   g_pxh);
    cudaGetSymbolAddress((void**)&y,     g_y);
    cudaGetSymbolAddress((void**)&ph,    g_ph);
    cudaGetSymbolAddress((void**)&ts,    g_ts);
    cudaGetSymbolAddress((void**)&hcat,  g_hcat);
    cudaGetSymbolAddress((void**)&pzh,   g_pzh);
    cudaGetSymbolAddress((void**)&wc,    g_wc);
    cudaGetSymbolAddress((void**)&cbias, g_cbias);
    cudaGetSymbolAddress((void**)&dis,   g_dis);
    cudaGetSymbolAddress((void**)&deg,   g_deg);
    cudaGetSymbolAddress((void**)&rp,    g_rowptr);
    cudaGetSymbolAddress((void**)&cur,   g_cursor);
    cudaGetSymbolAddress((void**)&col,   g_col);
    cudaGetSymbolAddress((void**)&bsum,  g_bsum);

    static bool inited = false;
    static cudaStream_t st1, st2;
    static cudaEvent_t evDis, evPre, evY, ev1, ev2;
    if (!inited) {
        cudaStreamCreateWithFlags(&st1, cudaStreamNonBlocking);
        cudaStreamCreateWithFlags(&st2, cudaStreamNonBlocking);
        cudaEventCreateWithFlags(&evDis, cudaEventDisableTiming);
        cudaEventCreateWithFlags(&evPre, cudaEventDisableTiming);
        cudaEventCreateWithFlags(&evY, cudaEventDisableTiming);
        cudaEventCreateWithFlags(&ev1, cudaEventDisableTiming);
        cudaEventCreateWithFlags(&ev2, cudaEventDisableTiming);
        cudaFuncSetAttribute(tgemm_kernel<128, 128, 3>,
                             cudaFuncAttributeMaxDynamicSharedMemorySize, SMEM_128);
        cudaFuncSetAttribute(tgemm_kernel<128, 128, 1>,
                             cudaFuncAttributeMaxDynamicSharedMemorySize, SMEM_128);
        cudaFuncSetAttribute(tgemm_kernel<384, 64, 2>,
                             cudaFuncAttributeMaxDynamicSharedMemorySize, SMEM_64);
        inited = true;
    }

    const int TB = 256;
    int nB = (N + TB - 1) / TB;
    int eB = (E + TB - 1) / TB;
    int nbScan = (N + SCAN_B - 1) / SCAN_B;
    int aggB = (N * 32 + TB - 1) / TB;
    int gB = (N + 127) / 128;

    cudaStream_t s0 = 0;

    // --- weight folding on st1 (no graph deps) ---
    wc_kernel<<<384, 64, 0, st1>>>(W2, Wf, wc);
    cbias_kernel<<<1, 64, 0, st1>>>(b2, Wf, bf, cbias);

    // --- graph prep on s0 ---
    zero_kernel<<<nB, TB, 0, s0>>>(deg, cur, N);
    count_kernel<<<eB, TB, 0, s0>>>(dst, deg, E);
    dis_kernel<<<nB, TB, 0, s0>>>(deg, dis, N);
    cudaEventRecord(evDis, s0);

    // prescale on st2, concurrent with scan/fill
    cudaStreamWaitEvent(st2, evDis, 0);
    prescale_h_kernel<<<(N * 32 + TB - 1) / TB, TB, 0, st2>>>(
        (const float4*)x, dis, (uint2*)pxh, N * 32);
    cudaEventRecord(evPre, st2);

    scan1_kernel<<<nbScan, SCAN_B, 0, s0>>>(deg, rp, bsum, N);
    scan2_kernel<<<1, 32, 0, s0>>>(bsum, nbScan);
    scan3_kernel<<<nB, TB, 0, s0>>>(rp, bsum, N);
    fill_kernel<<<eB, TB, 0, s0>>>(src, dst, rp, cur, col, E);

    // --- shared layer-0 aggregation: y = A_hat x  (fp16 gather) ---
    cudaStreamWaitEvent(s0, evPre, 0);
    agg128h_kernel<<<aggB, TB, 0, s0>>>(pxh, dis, rp, deg, col, y, N);
    cudaEventRecord(evY, s0);
    cudaStreamWaitEvent(st1, evY, 0);
    cudaStreamWaitEvent(st2, evY, 0);

    // --- per-scale chains on 3 streams ---
    cudaStream_t chain[3] = {s0, st1, st2};
    for (int s = 0; s < 3; s++) {
        cudaStream_t cs = chain[s];
        __half* ph_s = ph + (size_t)s * NN * 128;
        float* t_s = ts + (size_t)s * NN * 128;
        tgemm_kernel<128, 128, 3><<<gB, 256, SMEM_128, cs>>>(
            y, W0 + s * 128 * 128, dis, b0 + s * 128,
            gamma + (s * 3 + 0) * 128, beta + (s * 3 + 0) * 128,
            ph_s, 128, 0, N);
        agg128h_kernel<<<aggB, TB, 0, cs>>>(ph_s, dis, rp, deg, col, t_s, N);
        tgemm_kernel<128, 128, 1><<<gB, 256, SMEM_128, cs>>>(
            t_s, W1 + s * 128 * 128, dis, b1 + s * 128,
            gamma + (s * 3 + 1) * 128, beta + (s * 3 + 1) * 128,
            hcat, 384, s * 128, N);
    }
    cudaEventRecord(ev1, st1);
    cudaEventRecord(ev2, st2);
    cudaStreamWaitEvent(s0, ev1, 0);
    cudaStreamWaitEvent(s0, ev2, 0);

    // --- folded tail: pz(fp16) = dis * (hcat @ Wc); out = agg + cbias ---
    tgemm_kernel<384, 64, 2><<<gB, 256, SMEM_64, s0>>>(
        hcat, wc, dis, nullptr, nullptr, nullptr, pzh, 64, 0, N);
    agg64h_kernel<<<aggB, TB, 0, s0>>>((const uint32_t*)pzh, dis, rp, deg, col, cbias,
                                       (float2*)out, N);
}

// round 8
// speedup vs baseline: 3.3500x; 1.1962x over previous
#include <cuda_runtime.h>
#include <cuda_fp16.h>
#include <cstdint>

#define NN 100000
#define EE 3200000
#define SCAN_B 512
#define NBLK_SCAN ((NN + SCAN_B - 1) / SCAN_B)

// -------- device scratch (no cudaMalloc allowed) --------
__device__ __half g_pxh[NN * 128];       // fp16 dis-prescaled x
__device__ __half g_yh[NN * 128];        // y = A_hat x (fp16)
__device__ __half g_ph[3][NN * 128];     // per-scale dis*LN(relu(...)) fp16
__device__ __half g_th[3][NN * 128];     // per-scale t_s = A_hat ph_s (fp16)
__device__ __half g_hcath[NN * 384];     // fp16 concat
__device__ __half g_pzh[NN * 64];        // fp16 tail
__device__ float  g_wc[384 * 64];
__device__ __half g_w0h[3 * 128 * 128], g_w0l[3 * 128 * 128];
__device__ __half g_w1h[3 * 128 * 128], g_w1l[3 * 128 * 128];
__device__ __half g_wch[384 * 64],      g_wcl[384 * 64];
__device__ float  g_cbias[64];
__device__ float  g_dis[NN];
__device__ int    g_deg[NN];
__device__ int    g_rowptr[NN];
__device__ int    g_cursor[NN];
__device__ int    g_col[EE];
__device__ int    g_bsum[NBLK_SCAN + 1];

// ---------------------------------------------------------------------------
// graph prep
// ---------------------------------------------------------------------------
__global__ void zero_kernel(int* deg, int* cur, int n) {
    int i = blockIdx.x * blockDim.x + threadIdx.x;
    if (i < n) { deg[i] = 0; cur[i] = 0; }
}

__global__ void count_kernel(const int* __restrict__ dst, int* __restrict__ deg, int e) {
    int i = blockIdx.x * blockDim.x + threadIdx.x;
    if (i < e) atomicAdd(&deg[dst[i]], 1);
}

__global__ void dis_kernel(const int* __restrict__ deg, float* __restrict__ dis, int n) {
    int i = blockIdx.x * blockDim.x + threadIdx.x;
    if (i < n) dis[i] = rsqrtf((float)deg[i] + 1.0f);
}

__global__ void scan1_kernel(const int* __restrict__ deg, int* __restrict__ out,
                             int* __restrict__ bsum, int n) {
    __shared__ int sh[SCAN_B];
    int tid = threadIdx.x;
    int i = blockIdx.x * SCAN_B + tid;
    int v = (i < n) ? deg[i] : 0;
    sh[tid] = v;
    __syncthreads();
#pragma unroll
    for (int off = 1; off < SCAN_B; off <<= 1) {
        int t = (tid >= off) ? sh[tid - off] : 0;
        __syncthreads();
        sh[tid] += t;
        __syncthreads();
    }
    if (i < n) out[i] = sh[tid] - v;
    if (tid == SCAN_B - 1) bsum[blockIdx.x] = sh[tid];
}

__global__ void scan2_kernel(int* bsum, int nb) {
    if (threadIdx.x == 0 && blockIdx.x == 0) {
        int acc = 0;
        for (int i = 0; i < nb; i++) { int t = bsum[i]; bsum[i] = acc; acc += t; }
    }
}

__global__ void scan3_kernel(int* __restrict__ out, const int* __restrict__ bsum, int n) {
    int i = blockIdx.x * blockDim.x + threadIdx.x;
    if (i < n) out[i] += bsum[i / SCAN_B];
}

__global__ void fill_kernel(const int* __restrict__ src, const int* __restrict__ dst,
                            const int* __restrict__ rowptr, int* __restrict__ cur,
                            int* __restrict__ col, int e) {
    int i = blockIdx.x * blockDim.x + threadIdx.x;
    if (i < e) {
        int d = dst[i];
        int pos = rowptr[d] + atomicAdd(&cur[d], 1);
        col[pos] = src[i];
    }
}

// ---------------------------------------------------------------------------
// weight folding / conversion / prescale
// ---------------------------------------------------------------------------
__global__ void wc_kernel(const float* __restrict__ W2, const float* __restrict__ Wf,
                          float* __restrict__ Wc) {
    int r = blockIdx.x;
    int s = r >> 7, i = r & 127;
    int j = threadIdx.x;
    float acc = 0.0f;
#pragma unroll 8
    for (int k = 0; k < 64; k++)
        acc = fmaf(W2[(s * 128 + i) * 64 + k], Wf[(s * 64 + k) * 64 + j], acc);
    Wc[r * 64 + j] = acc;
}

__global__ void cbias_kernel(const float* __restrict__ b2, const float* __restrict__ Wf,
                             const float* __restrict__ bf, float* __restrict__ cb) {
    int j = threadIdx.x;
    float acc = bf[j];
#pragma unroll 8
    for (int r = 0; r < 192; r++) acc = fmaf(b2[r], Wf[r * 64 + j], acc);
    cb[j] = acc;
}

// split fp32 weights into fp16 hi + fp16 lo (residual)
__global__ void convh_kernel(const float* __restrict__ W, __half* __restrict__ Wh,
                             __half* __restrict__ Wl, int n) {
    int i = blockIdx.x * blockDim.x + threadIdx.x;
    if (i < n) {
        float w = W[i];
        __half h = __float2half_rn(w);
        Wh[i] = h;
        Wl[i] = __float2half_rn(w - __half2float(h));
    }
}

__global__ void prescale_h_kernel(const float4* __restrict__ x, const float* __restrict__ dis,
                                  uint2* __restrict__ px, int n4) {
    int i = blockIdx.x * blockDim.x + threadIdx.x;
    if (i < n4) {
        float s = dis[i >> 5];
        float4 v = x[i];
        __half2 h0 = __floats2half2_rn(v.x * s, v.y * s);
        __half2 h1 = __floats2half2_rn(v.z * s, v.w * s);
        uint2 u;
        u.x = *(uint32_t*)&h0; u.y = *(uint32_t*)&h1;
        px[i] = u;
    }
}

// ---------------------------------------------------------------------------
// fp16 tensor-core GEMM: A exactly fp16, W split fp16 hi/lo (2 MMA passes)
// EPI 1: LN(relu(acc+bias))            -> fp16 C (ldo/coloff)
// EPI 2: acc * dis[row]                -> fp16 C (row stride BN)
// EPI 3: LN(relu(acc+bias)) * dis[row] -> fp16 C (ldo/coloff)
// ---------------------------------------------------------------------------
__device__ __forceinline__ uint32_t smem_u32(const void* p) {
    uint32_t a;
    asm("{ .reg .u64 t; cvta.to.shared.u64 t, %1; cvt.u32.u64 %0, t; }"
        : "=r"(a) : "l"(p));
    return a;
}

#define LDSM_X4(r, addr)                                                      \
    asm volatile("ldmatrix.sync.aligned.m8n8.x4.shared.b16 {%0,%1,%2,%3}, [%4];" \
                 : "=r"((r)[0]), "=r"((r)[1]), "=r"((r)[2]), "=r"((r)[3])     \
                 : "r"(addr))

#define LDSM_X2T(r, addr)                                                     \
    asm volatile("ldmatrix.sync.aligned.m8n8.x2.trans.shared.b16 {%0,%1}, [%2];" \
                 : "=r"((r)[0]), "=r"((r)[1]) : "r"(addr))

#define MMA_F16(d, a, b)                                                      \
    asm volatile("mma.sync.aligned.m16n8k16.row.col.f32.f16.f16.f32 "         \
                 "{%0,%1,%2,%3}, {%4,%5,%6,%7}, {%8,%9}, {%0,%1,%2,%3};"      \
                 : "+f"((d)[0]), "+f"((d)[1]), "+f"((d)[2]), "+f"((d)[3])     \
                 : "r"((a)[0]), "r"((a)[1]), "r"((a)[2]), "r"((a)[3]),        \
                   "r"((b)[0]), "r"((b)[1]))

template <int KDIM, int BN, int EPI>
__global__ void __launch_bounds__(256)
tgemm_h_kernel(const __half* __restrict__ A, const __half* __restrict__ Wh,
               const __half* __restrict__ Wl,
               const float* __restrict__ dis, const float* __restrict__ bias,
               const float* __restrict__ gamma, const float* __restrict__ beta,
               __half* __restrict__ C, int ldo, int coloff, int nrows) {
    constexpr int LDA = 136;            // halves (+8 pad)
    constexpr int LDB = BN + 8;
    constexpr int WN = BN / 32;
    constexpr int WM = 8 / WN;
    constexpr int WROWS = 128 / WM;
    constexpr int MI = WROWS / 16;
    constexpr int NJ = 4;
    constexpr int ABYTES = 128 * LDA * 2;   // 34816
    constexpr int BBYTES = 128 * LDB * 2;
    constexpr int AH = 0, BH = ABYTES, BL = BH + BBYTES;
    constexpr int NU4 = BN / 8;             // uint4 per B row

    extern __shared__ char smem[];
    __shared__ float sh_bias[128], sh_g[128], sh_b[128];

    int tid = threadIdx.x, wid = tid >> 5, lane = tid & 31;
    int warp_m = wid % WM, warp_n = wid / WM;
    int m0 = blockIdx.x * 128;
    uint32_t sb = smem_u32(smem);

    if (EPI != 2 && tid < 128) {
        sh_bias[tid] = bias[tid];
        sh_g[tid] = gamma[tid];
        sh_b[tid] = beta[tid];
    }

    float acc[MI][NJ][4];
#pragma unroll
    for (int i = 0; i < MI; i++)
#pragma unroll
        for (int j = 0; j < NJ; j++)
#pragma unroll
            for (int k = 0; k < 4; k++) acc[i][j][k] = 0.0f;

    int a_r = lane & 15, a_c8 = (lane >> 4) * 8;
    int b_r = lane & 15;

    for (int kc = 0; kc < KDIM / 128; kc++) {
        if (kc) __syncthreads();
        // ---- stage A chunk: direct fp16 uint4 copy (128 rows x 16 uint4)
#pragma unroll
        for (int it = 0; it < 8; it++) {
            int idx = it * 256 + tid;
            int row = idx >> 4, u4 = idx & 15;
            int rg = m0 + row;
            uint4 v = make_uint4(0u, 0u, 0u, 0u);
            if (rg < nrows)
                v = *(const uint4*)(A + (size_t)rg * KDIM + kc * 128 + u4 * 8);
            *(uint4*)(smem + AH + (row * LDA + u4 * 8) * 2) = v;
        }
        // ---- stage B hi/lo chunks: direct fp16 uint4 copies
#pragma unroll
        for (int it = 0; it < (128 * NU4) / 256; it++) {
            int idx = it * 256 + tid;
            int k = idx / NU4, u4 = idx % NU4;
            size_t goff = (size_t)(kc * 128 + k) * BN + u4 * 8;
            int soff = (k * LDB + u4 * 8) * 2;
            *(uint4*)(smem + BH + soff) = *(const uint4*)(Wh + goff);
            *(uint4*)(smem + BL + soff) = *(const uint4*)(Wl + goff);
        }
        __syncthreads();

        // ---- 2 accumulation passes: A@Wh, A@Wl
#pragma unroll
        for (int p = 0; p < 2; p++) {
            uint32_t bB = sb + (p ? BL : BH);
#pragma unroll
            for (int ks = 0; ks < 8; ks++) {
                uint32_t af[MI][4], bf_[NJ][2];
#pragma unroll
                for (int mi = 0; mi < MI; mi++) {
                    uint32_t ad = sb + AH +
                        ((warp_m * WROWS + mi * 16 + a_r) * LDA + ks * 16 + a_c8) * 2;
                    LDSM_X4(af[mi], ad);
                }
#pragma unroll
                for (int nj = 0; nj < NJ; nj++) {
                    uint32_t bd = bB +
                        ((ks * 16 + b_r) * LDB + warp_n * 32 + nj * 8) * 2;
                    LDSM_X2T(bf_[nj], bd);
                }
#pragma unroll
                for (int mi = 0; mi < MI; mi++)
#pragma unroll
                    for (int nj = 0; nj < NJ; nj++)
                        MMA_F16(acc[mi][nj], af[mi], bf_[nj]);
            }
        }
    }

    int g = lane >> 2, q2 = (lane & 3) * 2;

    if (EPI == 2) {
#pragma unroll
        for (int mi = 0; mi < MI; mi++) {
#pragma unroll
            for (int nj = 0; nj < NJ; nj++) {
                int n = warp_n * 32 + nj * 8 + q2;
                int r0 = m0 + warp_m * WROWS + mi * 16 + g;
                if (r0 < nrows) {
                    float s = dis[r0];
                    __half2 h = __floats2half2_rn(acc[mi][nj][0] * s, acc[mi][nj][1] * s);
                    *(uint32_t*)(C + (size_t)r0 * BN + n) = *(uint32_t*)&h;
                }
                int r1 = r0 + 8;
                if (r1 < nrows) {
                    float s = dis[r1];
                    __half2 h = __floats2half2_rn(acc[mi][nj][2] * s, acc[mi][nj][3] * s);
                    *(uint32_t*)(C + (size_t)r1 * BN + n) = *(uint32_t*)&h;
                }
            }
        }
        return;
    }

    // LN epilogue via padded f32 smem buffer (reuses staging region)
    __syncthreads();
    float* Cs = (float*)smem;   // [128][129]
#pragma unroll
    for (int mi = 0; mi < MI; mi++)
#pragma unroll
        for (int nj = 0; nj < NJ; nj++) {
            int rl = warp_m * WROWS + mi * 16 + g;
            int n = warp_n * 32 + nj * 8 + q2;
            Cs[rl * 129 + n]           = acc[mi][nj][0];
            Cs[rl * 129 + n + 1]       = acc[mi][nj][1];
            Cs[(rl + 8) * 129 + n]     = acc[mi][nj][2];
            Cs[(rl + 8) * 129 + n + 1] = acc[mi][nj][3];
        }
    __syncthreads();

    int row = tid >> 1, half = tid & 1;
    float v[64];
    float s1 = 0.0f, s2 = 0.0f;
#pragma unroll
    for (int j = 0; j < 64; j++) {
        float t = fmaxf(Cs[row * 129 + half * 64 + j] + sh_bias[half * 64 + j], 0.0f);
        v[j] = t; s1 += t; s2 += t * t;
    }
    s1 += __shfl_xor_sync(0xffffffffu, s1, 1);
    s2 += __shfl_xor_sync(0xffffffffu, s2, 1);
    float mu = s1 * (1.0f / 128.0f);
    float var = s2 * (1.0f / 128.0f) - mu * mu;
    float inv = rsqrtf(var + 1e-5f);

    int rg = m0 + row;
    if (rg >= nrows) return;

    float sc = (EPI == 3) ? dis[rg] : 1.0f;
    __half* outp = C + (size_t)rg * ldo + coloff + half * 64;
#pragma unroll
    for (int j = 0; j < 64; j += 8) {
        float o[8];
#pragma unroll
        for (int q = 0; q < 8; q++)
            o[q] = ((v[j + q] - mu) * inv * sh_g[half * 64 + j + q]
                    + sh_b[half * 64 + j + q]) * sc;
        __half2 h0 = __floats2half2_rn(o[0], o[1]);
        __half2 h1 = __floats2half2_rn(o[2], o[3]);
        __half2 h2 = __floats2half2_rn(o[4], o[5]);
        __half2 h3 = __floats2half2_rn(o[6], o[7]);
        uint4 u;
        u.x = *(uint32_t*)&h0; u.y = *(uint32_t*)&h1;
        u.z = *(uint32_t*)&h2; u.w = *(uint32_t*)&h3;
        *(uint4*)(outp + j) = u;
    }
}

#define SMEMH_128 (34816 * 3)                       // 104448
#define SMEMH_64  (34816 + 2 * (128 * 72 * 2))      // 71680

// ---------------------------------------------------------------------------
// aggregation (warp per node)
// ---------------------------------------------------------------------------
// fp16 in (128-wide), fp16 out
__global__ void __launch_bounds__(256)
agg128hh_kernel(const __half* __restrict__ p, const float* __restrict__ dis,
                const int* __restrict__ rowptr, const int* __restrict__ deg,
                const int* __restrict__ col, __half* __restrict__ out, int n) {
    int w = (blockIdx.x * blockDim.x + threadIdx.x) >> 5;
    if (w >= n) return;
    int lane = threadIdx.x & 31;
    const uint2* p2 = (const uint2*)p;
    int start = rowptr[w], d = deg[w];
    uint2 a = p2[(size_t)w * 32 + lane];
    float2 f0 = __half22float2(*(__half2*)&a.x);
    float2 f1 = __half22float2(*(__half2*)&a.y);
    float ax = f0.x, ay = f0.y, az = f1.x, aw = f1.y;

    int c0 = 0;
    for (; c0 + 32 <= d; c0 += 32) {
        int idx = col[start + c0 + lane];
#pragma unroll 8
        for (int j = 0; j < 32; j++) {
            int u = __shfl_sync(0xffffffffu, idx, j);
            uint2 v = p2[(size_t)u * 32 + lane];
            float2 g0 = __half22float2(*(__half2*)&v.x);
            float2 g1 = __half22float2(*(__half2*)&v.y);
            ax += g0.x; ay += g0.y; az += g1.x; aw += g1.y;
        }
    }
    int m = d - c0;
    if (m > 0) {
        int idx = (lane < m) ? col[start + c0 + lane] : 0;
        for (int j = 0; j < m; j++) {
            int u = __shfl_sync(0xffffffffu, idx, j);
            uint2 v = p2[(size_t)u * 32 + lane];
            float2 g0 = __half22float2(*(__half2*)&v.x);
            float2 g1 = __half22float2(*(__half2*)&v.y);
            ax += g0.x; ay += g0.y; az += g1.x; aw += g1.y;
        }
    }
    float s = dis[w];
    __half2 h0 = __floats2half2_rn(ax * s, ay * s);
    __half2 h1 = __floats2half2_rn(az * s, aw * s);
    uint2 o;
    o.x = *(uint32_t*)&h0; o.y = *(uint32_t*)&h1;
    ((uint2*)out)[(size_t)w * 32 + lane] = o;
}

// merged 3-scale gather: reads ph0/1/2 (fp16 128-wide), writes t0/1/2 (fp16)
__global__ void __launch_bounds__(256)
agg384h_kernel(const __half* __restrict__ p0, const __half* __restrict__ p1,
               const __half* __restrict__ p2h, const float* __restrict__ dis,
               const int* __restrict__ rowptr, const int* __restrict__ deg,
               const int* __restrict__ col,
               __half* __restrict__ t0, __half* __restrict__ t1,
               __half* __restrict__ t2, int n) {
    int w = (blockIdx.x * blockDim.x + threadIdx.x) >> 5;
    if (w >= n) return;
    int lane = threadIdx.x & 31;
    const uint2* q0 = (const uint2*)p0;
    const uint2* q1 = (const uint2*)p1;
    const uint2* q2 = (const uint2*)p2h;
    int start = rowptr[w], d = deg[w];

    float acc[12];
    {
        uint2 a0 = q0[(size_t)w * 32 + lane];
        uint2 a1 = q1[(size_t)w * 32 + lane];
        uint2 a2 = q2[(size_t)w * 32 + lane];
        float2 f;
        f = __half22float2(*(__half2*)&a0.x); acc[0] = f.x;  acc[1] = f.y;
        f = __half22float2(*(__half2*)&a0.y); acc[2] = f.x;  acc[3] = f.y;
        f = __half22float2(*(__half2*)&a1.x); acc[4] = f.x;  acc[5] = f.y;
        f = __half22float2(*(__half2*)&a1.y); acc[6] = f.x;  acc[7] = f.y;
        f = __half22float2(*(__half2*)&a2.x); acc[8] = f.x;  acc[9] = f.y;
        f = __half22float2(*(__half2*)&a2.y); acc[10] = f.x; acc[11] = f.y;
    }

    int c0 = 0;
    for (; c0 + 32 <= d; c0 += 32) {
        int idx = col[start + c0 + lane];
#pragma unroll 4
        for (int j = 0; j < 32; j++) {
            int u = __shfl_sync(0xffffffffu, idx, j);
            size_t off = (size_t)u * 32 + lane;
            uint2 v0 = q0[off], v1 = q1[off], v2 = q2[off];
            float2 f;
            f = __half22float2(*(__half2*)&v0.x); acc[0] += f.x;  acc[1] += f.y;
            f = __half22float2(*(__half2*)&v0.y); acc[2] += f.x;  acc[3] += f.y;
            f = __half22float2(*(__half2*)&v1.x); acc[4] += f.x;  acc[5] += f.y;
            f = __half22float2(*(__half2*)&v1.y); acc[6] += f.x;  acc[7] += f.y;
            f = __half22float2(*(__half2*)&v2.x); acc[8] += f.x;  acc[9] += f.y;
            f = __half22float2(*(__half2*)&v2.y); acc[10] += f.x; acc[11] += f.y;
        }
    }
    int m = d - c0;
    if (m > 0) {
        int idx = (lane < m) ? col[start + c0 + lane] : 0;
        for (int j = 0; j < m; j++) {
            int u = __shfl_sync(0xffffffffu, idx, j);
            size_t off = (size_t)u * 32 + lane;
            uint2 v0 = q0[off], v1 = q1[off], v2 = q2[off];
            float2 f;
            f = __half22float2(*(__half2*)&v0.x); acc[0] += f.x;  acc[1] += f.y;
            f = __half22float2(*(__half2*)&v0.y); acc[2] += f.x;  acc[3] += f.y;
            f = __half22float2(*(__half2*)&v1.x); acc[4] += f.x;  acc[5] += f.y;
            f = __half22float2(*(__half2*)&v1.y); acc[6] += f.x;  acc[7] += f.y;
            f = __half22float2(*(__half2*)&v2.x); acc[8] += f.x;  acc[9] += f.y;
            f = __half22float2(*(__half2*)&v2.y); acc[10] += f.x; acc[11] += f.y;
        }
    }

    float s = dis[w];
    uint2 o;
    __half2 h0, h1;
    h0 = __floats2half2_rn(acc[0] * s, acc[1] * s);
    h1 = __floats2half2_rn(acc[2] * s, acc[3] * s);
    o.x = *(uint32_t*)&h0; o.y = *(uint32_t*)&h1;
    ((uint2*)t0)[(size_t)w * 32 + lane] = o;
    h0 = __floats2half2_rn(acc[4] * s, acc[5] * s);
    h1 = __floats2half2_rn(acc[6] * s, acc[7] * s);
    o.x = *(uint32_t*)&h0; o.y = *(uint32_t*)&h1;
    ((uint2*)t1)[(size_t)w * 32 + lane] = o;
    h0 = __floats2half2_rn(acc[8] * s, acc[9] * s);
    h1 = __floats2half2_rn(acc[10] * s, acc[11] * s);
    o.x = *(uint32_t*)&h0; o.y = *(uint32_t*)&h1;
    ((uint2*)t2)[(size_t)w * 32 + lane] = o;
}

// fp16 payload, 64-wide rows: final output fp32 + cbias
__global__ void __launch_bounds__(256)
agg64h_kernel(const uint32_t* __restrict__ p, const float* __restrict__ dis,
              const int* __restrict__ rowptr, const int* __restrict__ deg,
              const int* __restrict__ col, const float* __restrict__ cbias,
              float2* __restrict__ out, int n) {
    int w = (blockIdx.x * blockDim.x + threadIdx.x) >> 5;
    if (w >= n) return;
    int lane = threadIdx.x & 31;
    int start = rowptr[w], d = deg[w];
    uint32_t a = p[(size_t)w * 32 + lane];
    float2 f = __half22float2(*(__half2*)&a);
    float ax = f.x, ay = f.y;

    int c0 = 0;
    for (; c0 + 32 <= d; c0 += 32) {
        int idx = col[start + c0 + lane];
#pragma unroll 8
        for (int j = 0; j < 32; j++) {
            int u = __shfl_sync(0xffffffffu, idx, j);
            uint32_t v = p[(size_t)u * 32 + lane];
            float2 g = __half22float2(*(__half2*)&v);
            ax += g.x; ay += g.y;
        }
    }
    int m = d - c0;
    if (m > 0) {
        int idx = (lane < m) ? col[start + c0 + lane] : 0;
        for (int j = 0; j < m; j++) {
            int u = __shfl_sync(0xffffffffu, idx, j);
            uint32_t v = p[(size_t)u * 32 + lane];
            float2 g = __half22float2(*(__half2*)&v);
            ax += g.x; ay += g.y;
        }
    }
    float s = dis[w];
    float2 o = {ax * s + cbias[lane * 2], ay * s + cbias[lane * 2 + 1]};
    out[(size_t)w * 32 + lane] = o;
}

// ---------------------------------------------------------------------------
extern "C" void kernel_launch(void* const* d_in, const int* in_sizes, int n_in,
                              void* d_out, int out_size) {
    const float* x     = (const float*)d_in[0];
    const int*   ei    = (const int*)d_in[1];
    const float* W0    = (const float*)d_in[2];
    const float* b0    = (const float*)d_in[3];
    const float* W1    = (const float*)d_in[4];
    const float* b1    = (const float*)d_in[5];
    const float* W2    = (const float*)d_in[6];
    const float* b2    = (const float*)d_in[7];
    const float* gamma = (const float*)d_in[8];
    const float* beta  = (const float*)d_in[9];
    const float* Wf    = (const float*)d_in[10];
    const float* bf    = (const float*)d_in[11];
    float* out = (float*)d_out;

    const int N = in_sizes[0] / 128;
    const int E = in_sizes[1] / 2;
    const int* src = ei;
    const int* dst = ei + E;

    __half *pxh, *yh, *ph, *th, *hcath, *pzh;
    __half *w0h, *w0l, *w1h, *w1l, *wch, *wcl;
    float *wc, *cbias, *dis;
    int *deg, *rp, *cur, *col, *bsum;
    cudaGetSymbolAddress((void**)&pxh,   g_pxh);
    cudaGetSymbolAddress((void**)&yh,    g_yh);
    cudaGetSymbolAddress((void**)&ph,    g_ph);
    cudaGetSymbolAddress((void**)&th,    g_th);
    cudaGetSymbolAddress((void**)&hcath, g_hcath);
    cudaGetSymbolAddress((void**)&pzh,   g_pzh);
    cudaGetSymbolAddress((void**)&wc,    g_wc);
    cudaGetSymbolAddress((void**)&w0h,   g_w0h);
    cudaGetSymbolAddress((void**)&w0l,   g_w0l);
    cudaGetSymbolAddress((void**)&w1h,   g_w1h);
    cudaGetSymbolAddress((void**)&w1l,   g_w1l);
    cudaGetSymbolAddress((void**)&wch,   g_wch);
    cudaGetSymbolAddress((void**)&wcl,   g_wcl);
    cudaGetSymbolAddress((void**)&cbias, g_cbias);
    cudaGetSymbolAddress((void**)&dis,   g_dis);
    cudaGetSymbolAddress((void**)&deg,   g_deg);
    cudaGetSymbolAddress((void**)&rp,    g_rowptr);
    cudaGetSymbolAddress((void**)&cur,   g_cursor);
    cudaGetSymbolAddress((void**)&col,   g_col);
    cudaGetSymbolAddress((void**)&bsum,  g_bsum);

    static bool inited = false;
    static cudaStream_t st1, st2;
    static cudaEvent_t evRoot, evDis, evPre, evW, evY, evG1, evG2, evT, ev1, ev2;
    if (!inited) {
        cudaStreamCreateWithFlags(&st1, cudaStreamNonBlocking);
        cudaStreamCreateWithFlags(&st2, cudaStreamNonBlocking);
        cudaEventCreateWithFlags(&evRoot, cudaEventDisableTiming);
        cudaEventCreateWithFlags(&evDis, cudaEventDisableTiming);
        cudaEventCreateWithFlags(&evPre, cudaEventDisableTiming);
        cudaEventCreateWithFlags(&evW,  cudaEventDisableTiming);
        cudaEventCreateWithFlags(&evY,  cudaEventDisableTiming);
        cudaEventCreateWithFlags(&evG1, cudaEventDisableTiming);
        cudaEventCreateWithFlags(&evG2, cudaEventDisableTiming);
        cudaEventCreateWithFlags(&evT,  cudaEventDisableTiming);
        cudaEventCreateWithFlags(&ev1,  cudaEventDisableTiming);
        cudaEventCreateWithFlags(&ev2,  cudaEventDisableTiming);
        cudaFuncSetAttribute(tgemm_h_kernel<128, 128, 3>,
                             cudaFuncAttributeMaxDynamicSharedMemorySize, SMEMH_128);
        cudaFuncSetAttribute(tgemm_h_kernel<128, 128, 1>,
                             cudaFuncAttributeMaxDynamicSharedMemorySize, SMEMH_128);
        cudaFuncSetAttribute(tgemm_h_kernel<384, 64, 2>,
                             cudaFuncAttributeMaxDynamicSharedMemorySize, SMEMH_64);
        inited = true;
    }

    const int TB = 256;
    int nB = (N + TB - 1) / TB;
    int eB = (E + TB - 1) / TB;
    int nbScan = (N + SCAN_B - 1) / SCAN_B;
    int aggB = (N * 32 + TB - 1) / TB;
    int gB = (N + 127) / 128;

    cudaStream_t s0 = 0;

    // --- CAPTURE FORK: st1 must be forked from the origin stream before any
    //     launch on it, or graph capture fails. ---
    zero_kernel<<<nB, TB, 0, s0>>>(deg, cur, N);     // first origin-stream node
    cudaEventRecord(evRoot, s0);
    cudaStreamWaitEvent(st1, evRoot, 0);

    // --- weight folding + fp16 hi/lo conversion on st1 ---
    wc_kernel<<<384, 64, 0, st1>>>(W2, Wf, wc);
    cbias_kernel<<<1, 64, 0, st1>>>(b2, Wf, bf, cbias);
    convh_kernel<<<(3 * 128 * 128 + 255) / 256, 256, 0, st1>>>(W0, w0h, w0l, 3 * 128 * 128);
    convh_kernel<<<(3 * 128 * 128 + 255) / 256, 256, 0, st1>>>(W1, w1h, w1l, 3 * 128 * 128);
    convh_kernel<<<(384 * 64 + 255) / 256, 256, 0, st1>>>(wc, wch, wcl, 384 * 64);
    cudaEventRecord(evW, st1);

    // --- graph prep on s0 ---
    count_kernel<<<eB, TB, 0, s0>>>(dst, deg, E);
    dis_kernel<<<nB, TB, 0, s0>>>(deg, dis, N);
    cudaEventRecord(evDis, s0);

    // prescale on st2, concurrent with scan/fill (fork via evDis)
    cudaStreamWaitEvent(st2, evDis, 0);
    prescale_h_kernel<<<(N * 32 + TB - 1) / TB, TB, 0, st2>>>(
        (const float4*)x, dis, (uint2*)pxh, N * 32);
    cudaEventRecord(evPre, st2);

    scan1_kernel<<<nbScan, SCAN_B, 0, s0>>>(deg, rp, bsum, N);
    scan2_kernel<<<1, 32, 0, s0>>>(bsum, nbScan);
    scan3_kernel<<<nB, TB, 0, s0>>>(rp, bsum, N);
    fill_kernel<<<eB, TB, 0, s0>>>(src, dst, rp, cur, col, E);

    // --- shared layer-0 aggregation: yh = A_hat x (fp16 in/out) ---
    cudaStreamWaitEvent(s0, evPre, 0);
    agg128hh_kernel<<<aggB, TB, 0, s0>>>(pxh, dis, rp, deg, col, yh, N);
    cudaEventRecord(evY, s0);

    // --- GEMM0 x3 on 3 streams (need weights + yh) ---
    cudaStreamWaitEvent(s0, evW, 0);
    cudaStreamWaitEvent(st1, evY, 0);
    cudaStreamWaitEvent(st2, evY, 0);
    cudaStreamWaitEvent(st2, evW, 0);
    cudaStream_t chain[3] = {s0, st1, st2};
    for (int s = 0; s < 3; s++) {
        tgemm_h_kernel<128, 128, 3><<<gB, 256, SMEMH_128, chain[s]>>>(
            yh, w0h + s * 16384, w0l + s * 16384, dis, b0 + s * 128,
            gamma + (s * 3 + 0) * 128, beta + (s * 3 + 0) * 128,
            ph + (size_t)s * NN * 128, 128, 0, N);
    }
    cudaEventRecord(evG1, st1);
    cudaEventRecord(evG2, st2);
    cudaStreamWaitEvent(s0, evG1, 0);
    cudaStreamWaitEvent(s0, evG2, 0);

    // --- merged 3-scale mid aggregation ---
    agg384h_kernel<<<aggB, TB, 0, s0>>>(
        ph, ph + (size_t)NN * 128, ph + (size_t)2 * NN * 128, dis, rp, deg, col,
        th, th + (size_t)NN * 128, th + (size_t)2 * NN * 128, N);
    cudaEventRecord(evT, s0);
    cudaStreamWaitEvent(st1, evT, 0);
    cudaStreamWaitEvent(st2, evT, 0);

    // --- GEMM1 x3 on 3 streams ---
    for (int s = 0; s < 3; s++) {
        tgemm_h_kernel<128, 128, 1><<<gB, 256, SMEMH_128, chain[s]>>>(
            th + (size_t)s * NN * 128, w1h + s * 16384, w1l + s * 16384,
            dis, b1 + s * 128,
            gamma + (s * 3 + 1) * 128, beta + (s * 3 + 1) * 128,
            hcath, 384, s * 128, N);
    }
    cudaEventRecord(ev1, st1);
    cudaEventRecord(ev2, st2);
    cudaStreamWaitEvent(s0, ev1, 0);
    cudaStreamWaitEvent(s0, ev2, 0);

    // --- folded tail: pzh = dis * (hcath @ Wc); out = agg + cbias ---
    tgemm_h_kernel<384, 64, 2><<<gB, 256, SMEMH_64, s0>>>(
        hcath, wch, wcl, dis, nullptr, nullptr, nullptr, pzh, 64, 0, N);
    agg64h_kernel<<<aggB, TB, 0, s0>>>((const uint32_t*)pzh, dis, rp, deg, col, cbias,
                                       (float2*)out, N);
}